// round 15
// baseline (speedup 1.0000x reference)
#include <cuda_runtime.h>
#include <cuda_bf16.h>
#include <cstdint>

// Arch gate: tcgen05 only exists in the sm_103a/sm_100a-specific passes.
#if !defined(__CUDA_ARCH__) || defined(__CUDA_ARCH_FEAT_SM103_ALL) || defined(__CUDA_ARCH_FEAT_SM100_ALL)
#define TC_OK 1
#else
#define TC_OK 0
#endif

// Problem constants
#define NB 2
#define TT 2048
#define DMD 1024
#define HH 8
#define EE 4
#define LL 32
#define DD 64
#define NT (NB*TT)      // 4096
#define HD (HH*DD)      // 512

// ---------------- scratch (device globals; no allocation allowed) ----------
__device__ float g_K[NT*HD];
__device__ float g_V[NT*HD];
__device__ float g_Q[NT*HD];
__device__ float g_Gpre[NT*HD];     // raw G scores in cols [0,32) of each 512-row
__device__ float g_A[NB*EE*TT];
__device__ float g_gK[NB*EE*TT*DD];
__device__ float g_gV[NB*EE*TT*DD];
__device__ float g_Y[NT*HD];

// scan outputs as bf16 hi/lo (consumed by tensor attention)
__device__ __nv_bfloat16 g_sKh[NB*EE*TT*DD], g_sKl[NB*EE*TT*DD];
__device__ __nv_bfloat16 g_sVh[NB*EE*TT*DD], g_sVl[NB*EE*TT*DD];

// bf16 split operands for tensor-core GEMMs
// W layout: [wK 512 | wV 512 | wQ 512 | wG 32 + zero-pad 96] rows of 1024
__device__ __nv_bfloat16 g_Xh[NT*DMD], g_Xl[NT*DMD];
__device__ __nv_bfloat16 g_Wh[(3*HD + 128)*DMD], g_Wl[(3*HD + 128)*DMD];
__device__ __nv_bfloat16 g_WOh[DMD*HD], g_WOl[DMD*HD];
__device__ __nv_bfloat16 g_Yh[NT*HD], g_Yl[NT*HD];

// ---------------- PTX helpers ----------------------------------------------
__device__ __forceinline__ uint32_t smem_u32(const void* p) {
    uint32_t a;
    asm("{ .reg .u64 t; cvta.to.shared.u64 t, %1; cvt.u32.u64 %0, t; }"
        : "=r"(a) : "l"(p));
    return a;
}
__device__ __forceinline__ uint32_t elect_one() {
    uint32_t pred;
    asm volatile("{ .reg .pred p; elect.sync _|p, 0xFFFFFFFF; selp.b32 %0, 1, 0, p; }"
                 : "=r"(pred));
    return pred;
}
#define MB_INIT(mb, cnt) \
    asm volatile("mbarrier.init.shared.b64 [%0], %1;" :: "r"(mb), "r"(cnt) : "memory")
#define FENCE_ASYNC()     asm volatile("fence.proxy.async.shared::cta;" ::: "memory")
#define CPA16(dst, src) \
    asm volatile("cp.async.cg.shared.global [%0], [%1], 16;" :: "r"(dst), "l"(src) : "memory")
#define CPA_COMMIT() asm volatile("cp.async.commit_group;" ::: "memory")
#define CPA_WAIT0()  asm volatile("cp.async.wait_group 0;" ::: "memory")

__device__ __forceinline__ void mb_wait(uint32_t mb, uint32_t parity) {
    uint32_t done;
    asm volatile("{ .reg .pred p; mbarrier.try_wait.parity.acquire.cta.shared::cta.b64 p, [%1], %2;"
                 " selp.b32 %0, 1, 0, p; }" : "=r"(done) : "r"(mb), "r"(parity) : "memory");
    if (!done) {
        asm volatile("{ .reg .pred P1; WL%=:"
                     " mbarrier.try_wait.parity.acquire.cta.shared::cta.b64 P1, [%0], %1, 0x989680;"
                     " @P1 bra.uni WD%=; bra.uni WL%=; WD%=: }"
                     :: "r"(mb), "r"(parity) : "memory");
    }
}

#if TC_OK
#define TC_ALLOC(sm, n) \
    asm volatile("tcgen05.alloc.cta_group::1.sync.aligned.shared::cta.b32 [%0], %1;" \
                 :: "r"(sm), "r"(n) : "memory")
#define TC_DEALLOC(tm, n) \
    asm volatile("tcgen05.dealloc.cta_group::1.sync.aligned.b32 %0, %1;" :: "r"(tm), "r"(n))
#define TC_RELINQ() \
    asm volatile("tcgen05.relinquish_alloc_permit.cta_group::1.sync.aligned;")
#define TC_COMMIT(mb) \
    asm volatile("tcgen05.commit.cta_group::1.mbarrier::arrive::one.shared::cluster.b64 [%0];" \
                 :: "r"(mb) : "memory")
#define TC_FENCE_AFTER()  asm volatile("tcgen05.fence::after_thread_sync;" ::: "memory")
#define TC_FENCE_BEFORE() asm volatile("tcgen05.fence::before_thread_sync;" ::: "memory")
#define TC_WAIT_LD()      asm volatile("tcgen05.wait::ld.sync.aligned;" ::: "memory")

__device__ __forceinline__ void mma_f16_ss(uint32_t d, uint64_t ad, uint64_t bd,
                                           uint32_t idesc, uint32_t en) {
    asm volatile("{ .reg .pred p; setp.ne.u32 p, %5, 0;"
                 " tcgen05.mma.cta_group::1.kind::f16 [%0], %1, %2, %3, {%4,%4,%4,%4}, p; }"
                 :: "r"(d), "l"(ad), "l"(bd), "r"(idesc), "r"(0u), "r"(en) : "memory");
}
__device__ __forceinline__ void tc_ld32(uint32_t* r, uint32_t addr) {
    asm volatile("tcgen05.ld.sync.aligned.32x32b.x32.b32 "
        "{%0,%1,%2,%3,%4,%5,%6,%7,%8,%9,%10,%11,%12,%13,%14,%15,"
        "%16,%17,%18,%19,%20,%21,%22,%23,%24,%25,%26,%27,%28,%29,%30,%31}, [%32];"
        : "=r"(r[0]),"=r"(r[1]),"=r"(r[2]),"=r"(r[3]),"=r"(r[4]),"=r"(r[5]),"=r"(r[6]),"=r"(r[7]),
          "=r"(r[8]),"=r"(r[9]),"=r"(r[10]),"=r"(r[11]),"=r"(r[12]),"=r"(r[13]),"=r"(r[14]),"=r"(r[15]),
          "=r"(r[16]),"=r"(r[17]),"=r"(r[18]),"=r"(r[19]),"=r"(r[20]),"=r"(r[21]),"=r"(r[22]),"=r"(r[23]),
          "=r"(r[24]),"=r"(r[25]),"=r"(r[26]),"=r"(r[27]),"=r"(r[28]),"=r"(r[29]),"=r"(r[30]),"=r"(r[31])
        : "r"(addr));
}
#endif // TC_OK

static constexpr uint64_t DESC_BASE_SW128 =
    (uint64_t(2) << 61) | (uint64_t(1) << 46) | (uint64_t(64) << 32) | (uint64_t(1) << 16);
#define MK_DESC(a) (DESC_BASE_SW128 | ((uint64_t)((a) >> 4) & 0x3FFF))
#define SWZ(o) ((o) ^ (((o) >> 3) & 0x70))

// idesc: F32 accum, BF16 a/b, M=128; N field = (N/8)<<17
#define ID_N128 0x8200490u
#define ID_N192 0x8300490u
#define ID_N64  0x8100490u

__device__ __forceinline__ void split1(float x, __nv_bfloat16& h, __nv_bfloat16& l) {
    h = __float2bfloat16(x);
    l = __float2bfloat16(x - __bfloat162float(h));
}
__device__ __forceinline__ uint32_t packhl(__nv_bfloat16 a, __nv_bfloat16 b) {
    __nv_bfloat162 t(a, b);
    return *(uint32_t*)&t;
}

// ---------------- split kernels --------------------------------------------
__global__ __launch_bounds__(256) void split_all(
    const float* __restrict__ X,
    const float* __restrict__ wK, const float* __restrict__ wV,
    const float* __restrict__ wQ, const float* __restrict__ wG,
    const float* __restrict__ wO)
{
    __shared__ float t[32][33];
    int b = blockIdx.x;
    if (b >= 5760) {                      // wO transpose-split
        int j = b - 5760;
        int n0 = (j & 31) * 32, k0 = (j >> 5) * 32;
        int tx = threadIdx.x & 31, ty = threadIdx.x >> 5;
        #pragma unroll
        for (int jj = 0; jj < 32; jj += 8)
            t[ty + jj][tx] = wO[(k0 + ty + jj) * DMD + n0 + tx];
        __syncthreads();
        #pragma unroll
        for (int jj = 0; jj < 32; jj += 8) {
            __nv_bfloat16 h, l;
            split1(t[tx][ty + jj], h, l);
            g_WOh[(n0 + ty + jj) * HD + k0 + tx] = h;
            g_WOl[(n0 + ty + jj) * HD + k0 + tx] = l;
        }
        return;
    }
    if (b >= 5664) {                      // zero-pad
        int i = ((b - 5664) * 256 + threadIdx.x) * 4;
        size_t o = (size_t)(3*HD + 32) * DMD + i;
        *(uint64_t*)(g_Wh + o) = 0ull;
        *(uint64_t*)(g_Wl + o) = 0ull;
        return;
    }
    const float* s;
    __nv_bfloat16 *h, *l;
    int i;
    if (b < 4096) {
        s = X; h = g_Xh; l = g_Xl;
        i = b * 256 + threadIdx.x;
    } else if (b < 5632) {
        int j = b - 4096;
        int mat = j >> 9;
        s = (mat == 0) ? wK : (mat == 1) ? wV : wQ;
        h = g_Wh + (size_t)mat * HD * DMD;
        l = g_Wl + (size_t)mat * HD * DMD;
        i = (j & 511) * 256 + threadIdx.x;
    } else {                              // wG: 32 rows x 1024 = 8192 float4
        s = wG;
        h = g_Wh + (size_t)3 * HD * DMD;
        l = g_Wl + (size_t)3 * HD * DMD;
        i = (b - 5632) * 256 + threadIdx.x;
    }
    i <<= 2;
    float4 v = *(const float4*)(s + i);
    float xs[4] = {v.x, v.y, v.z, v.w};
    __nv_bfloat16 hh[4], ll[4];
    #pragma unroll
    for (int j = 0; j < 4; j++) split1(xs[j], hh[j], ll[j]);
    ((__nv_bfloat162*)(h + i))[0] = __nv_bfloat162(hh[0], hh[1]);
    ((__nv_bfloat162*)(h + i))[1] = __nv_bfloat162(hh[2], hh[3]);
    ((__nv_bfloat162*)(l + i))[0] = __nv_bfloat162(ll[0], ll[1]);
    ((__nv_bfloat162*)(l + i))[1] = __nv_bfloat162(ll[2], ll[3]);
}

// ---------------- tcgen05 GEMM (sm_103a pass only) -------------------------
// PROVEN BEST: 128x128 tiles, single 64KB stage, occ-3 — cross-CTA overlap.
// col_off selects the starting column tile (for split K/V | G | Q launches).
#define TC_SMEM (1024 + 65536)

__global__ __launch_bounds__(256, 3) void tc_gemm(
    const __nv_bfloat16* __restrict__ Ah, const __nv_bfloat16* __restrict__ Al,
    const __nv_bfloat16* __restrict__ Bh, const __nv_bfloat16* __restrict__ Bl,
    int K, float* C0, float* C1, float* C2, float* C3, int colmat, int col_off)
{
#if TC_OK
    extern __shared__ char smem[];
    uint32_t sb = smem_u32(smem);
    const int tid = threadIdx.x, wid = tid >> 5, lid = tid & 31;
    const int row0 = blockIdx.y * 128, col0 = (blockIdx.x + col_off) * 128;

    if (wid == 0) { TC_ALLOC(sb, 128); TC_RELINQ(); }
    __syncthreads();
    uint32_t tmem;
    asm volatile("ld.shared.b32 %0, [%1];" : "=r"(tmem) : "r"(sb));
    if (tid == 0) MB_INIT(sb + 8, 1);
    __syncthreads();

    const __nv_bfloat16* src[4] = { Ah + (size_t)row0 * K, Al + (size_t)row0 * K,
                                    Bh + (size_t)col0 * K, Bl + (size_t)col0 * K };
    const int NC = K >> 6;
    uint32_t stb = sb + 1024;
    uint64_t dA[2] = { MK_DESC(stb), MK_DESC(stb + 16384) };
    uint64_t dB[2] = { MK_DESC(stb + 32768), MK_DESC(stb + 49152) };

    int ph = 0;
    for (int c = 0; c < NC; c++) {
        if (c > 0) { mb_wait(sb + 8, ph); ph ^= 1; }
        int kof = c * 64;
        #pragma unroll
        for (int u = tid; u < 4096; u += 256) {
            int buf = u >> 10, wi = u & 1023;
            int r = wi >> 3, cb = wi & 7;
            uint32_t off = SWZ((uint32_t)(r * 128 + cb * 16));
            CPA16(stb + buf * 16384 + off, src[buf] + (size_t)r * K + kof + cb * 8);
        }
        CPA_COMMIT();
        CPA_WAIT0();
        FENCE_ASYNC();
        __syncthreads();
        if (wid == 0 && elect_one()) {
            #pragma unroll
            for (int ks = 0; ks < 4; ks++)
                mma_f16_ss(tmem, dA[0] + ks * 2, dB[0] + ks * 2, ID_N128, !(c == 0 && ks == 0));
            #pragma unroll
            for (int ks = 0; ks < 4; ks++)
                mma_f16_ss(tmem, dA[0] + ks * 2, dB[1] + ks * 2, ID_N128, 1);
            #pragma unroll
            for (int ks = 0; ks < 4; ks++)
                mma_f16_ss(tmem, dA[1] + ks * 2, dB[0] + ks * 2, ID_N128, 1);
            TC_COMMIT(sb + 8);
        }
        __syncthreads();
    }
    mb_wait(sb + 8, ph);
    TC_FENCE_AFTER();

    if (wid < 4) {
        int mat = col0 / colmat;
        float* C = (mat == 0) ? C0 : (mat == 1) ? C1 : (mat == 2) ? C2 : C3;
        int lc0 = col0 - mat * colmat;
        float* dst = C + (size_t)(row0 + wid * 32 + lid) * colmat + lc0;
        #pragma unroll
        for (int pass = 0; pass < 4; pass++) {
            uint32_t r[32];
            tc_ld32(r, tmem + pass * 32);
            TC_WAIT_LD();
            #pragma unroll
            for (int j = 0; j < 8; j++)
                *(float4*)&dst[pass * 32 + j * 4] =
                    make_float4(__uint_as_float(r[j*4]),   __uint_as_float(r[j*4+1]),
                                __uint_as_float(r[j*4+2]), __uint_as_float(r[j*4+3]));
        }
        TC_FENCE_BEFORE();
    }
    __syncthreads();
    if (wid == 0) TC_DEALLOC(tmem, 128);
#endif // TC_OK
}

// ---------------- tensor-core windowed attention (sm_103a pass) ------------
#define D2T 192              // TMEM col offset of AV accumulator
#define AVH 1024
#define AVL (AVH + 24576)    // 25600
#define AQH 50176
#define AQL (AQH + 16384)    // 66560
#define AKH (AQL + 16384)    // 82944
#define AKL (AKH + 24576)    // 107520
#define APH 50176            // reuse Q/K region after MMA1
#define APL (APH + 49152)    // 99328
#define ATC_SMEM 148480

__global__ __launch_bounds__(256) void attn_tc(
    const float* __restrict__ iK, const float* __restrict__ iV)
{
#if TC_OK
    extern __shared__ char smem[];
    uint32_t sb = smem_u32(smem);
    const int tid = threadIdx.x, wid = tid >> 5, lane = tid & 31;
    const int n = blockIdx.y, t0 = blockIdx.x * 16;

    if (wid == 0) { TC_ALLOC(sb, 256); TC_RELINQ(); }
    __syncthreads();
    uint32_t tmem;
    asm volatile("ld.shared.b32 %0, [%1];" : "=r"(tmem) : "r"(sb));
    if (tid == 0) { MB_INIT(sb + 8, 1); MB_INIT(sb + 16, 1); }

    // --- stage Q (scaled by 1/8, hi/lo split), rows m = h*16+tq, SW128 ---
    for (int idx = tid; idx < 128 * 32; idx += 256) {
        int m = idx >> 5, d2 = (idx & 31) * 2;
        int h = m >> 4, tq = m & 15;
        const float* qp = &g_Q[(size_t)(n * TT + t0 + tq) * HD + h * 64 + d2];
        float x0 = qp[0] * 0.125f, x1 = qp[1] * 0.125f;
        __nv_bfloat16 h0, l0, h1, l1;
        split1(x0, h0, l0); split1(x1, h1, l1);
        uint32_t off = SWZ((uint32_t)(m * 128 + d2 * 2));
        *(uint32_t*)(smem + AQH + off) = packhl(h0, h1);
        *(uint32_t*)(smem + AQL + off) = packhl(l0, l1);
    }
    // --- stage K rows (key rr = e*48+r), 16B granules, SW128 K-major ---
    for (int idx = tid; idx < 192 * 8; idx += 256) {
        int rr = idx >> 3, gc = idx & 7;
        int e = rr / 48, r = rr - e * 48;
        int s = t0 - 31 + r;
        uint32_t off = SWZ((uint32_t)(rr * 128 + gc * 16));
        uint4 vh, vl;
        if (r == 47) {
            vh = make_uint4(0, 0, 0, 0); vl = vh;
        } else if (s >= 0) {
            size_t g = ((size_t)(n * EE + e) * TT + s) * 64 + gc * 8;
            vh = *(const uint4*)&g_sKh[g];
            vl = *(const uint4*)&g_sKl[g];
        } else {
            const float* ip = &iK[(size_t)(e * 32 + (s + 32)) * 64 + gc * 8];
            float4 f0 = *(const float4*)ip, f1 = *(const float4*)(ip + 4);
            float fx[8] = {f0.x, f0.y, f0.z, f0.w, f1.x, f1.y, f1.z, f1.w};
            uint32_t hw[4], lw[4];
            #pragma unroll
            for (int j = 0; j < 4; j++) {
                __nv_bfloat16 a, b, c2, d2b;
                split1(fx[2*j], a, b); split1(fx[2*j+1], c2, d2b);
                hw[j] = packhl(a, c2);
                lw[j] = packhl(b, d2b);
            }
            vh = make_uint4(hw[0], hw[1], hw[2], hw[3]);
            vl = make_uint4(lw[0], lw[1], lw[2], lw[3]);
        }
        *(uint4*)(smem + AKH + off) = vh;
        *(uint4*)(smem + AKL + off) = vl;
    }
    // --- stage V as B-operand blocked atoms: [64 dims] x [192 keys] ---
    for (int idx = tid; idx < 192 * 64; idx += 256) {
        int d = idx & 63, rr = idx >> 6;
        int e = rr / 48, r = rr - e * 48;
        int s = t0 - 31 + r;
        int atom = (d >> 3) + (rr >> 6) * 8;
        uint32_t off = SWZ((uint32_t)(atom * 1024 + (d & 7) * 128 + (rr & 63) * 2));
        __nv_bfloat16 vh, vl;
        if (r == 47) {
            vh = __float2bfloat16(0.f); vl = vh;
        } else if (s >= 0) {
            size_t g = ((size_t)(n * EE + e) * TT + s) * 64 + d;
            vh = g_sVh[g]; vl = g_sVl[g];
        } else {
            split1(iV[(size_t)(e * 32 + (s + 32)) * 64 + d], vh, vl);
        }
        *(__nv_bfloat16*)(smem + AVH + off) = vh;
        *(__nv_bfloat16*)(smem + AVL + off) = vl;
    }
    FENCE_ASYNC();
    __syncthreads();

    // --- MMA1: scores D1[128x192] = Q * K^T (3-term split) ---
    if (wid == 0 && elect_one()) {
        uint64_t dQh = MK_DESC(sb + AQH), dQl = MK_DESC(sb + AQL);
        uint64_t dKh = MK_DESC(sb + AKH), dKl = MK_DESC(sb + AKL);
        #pragma unroll
        for (int ks = 0; ks < 4; ks++)
            mma_f16_ss(tmem, dQh + ks * 2, dKh + ks * 2, ID_N192, ks != 0);
        #pragma unroll
        for (int ks = 0; ks < 4; ks++)
            mma_f16_ss(tmem, dQh + ks * 2, dKl + ks * 2, ID_N192, 1);
        #pragma unroll
        for (int ks = 0; ks < 4; ks++)
            mma_f16_ss(tmem, dQl + ks * 2, dKh + ks * 2, ID_N192, 1);
        TC_COMMIT(sb + 8);
    }
    mb_wait(sb + 8, 0);
    TC_FENCE_AFTER();

    // --- softmax: pass 1 row-max, pass 2 exp(s-mx) -> P (hi/lo) in SMEM ---
    float ssum = 0.f;
    if (wid < 4) {
        const int m = wid * 32 + lane;
        const int tq = m & 15;
        float mx = -1e30f;
        #pragma unroll
        for (int cc = 0; cc < 6; cc++) {
            uint32_t r32[32];
            tc_ld32(r32, tmem + cc * 32);
            TC_WAIT_LD();
            #pragma unroll
            for (int j = 0; j < 32; j++) {
                int c = cc * 32 + j;
                int r = c % 48;
                float sv = __uint_as_float(r32[j]);
                if (((unsigned)(r - tq)) < 32u) mx = fmaxf(mx, sv);
            }
        }
        const int arow = m >> 3;
        const uint32_t ibase = (uint32_t)((m & 7) * 128);
        #pragma unroll
        for (int cc = 0; cc < 6; cc++) {
            uint32_t r32[32];
            tc_ld32(r32, tmem + cc * 32);
            TC_WAIT_LD();
            #pragma unroll
            for (int jp = 0; jp < 16; jp++) {
                int k = cc * 32 + jp * 2;
                float ev0, ev1;
                {
                    int r = k % 48;
                    float sv = __uint_as_float(r32[jp * 2]);
                    ev0 = (((unsigned)(r - tq)) < 32u) ? __expf(sv - mx) : 0.f;
                }
                {
                    int r = (k + 1) % 48;
                    float sv = __uint_as_float(r32[jp * 2 + 1]);
                    ev1 = (((unsigned)(r - tq)) < 32u) ? __expf(sv - mx) : 0.f;
                }
                ssum += ev0 + ev1;
                __nv_bfloat16 h0, l0, h1, l1;
                split1(ev0, h0, l0); split1(ev1, h1, l1);
                uint32_t off = SWZ((uint32_t)(((k >> 6) * 16 + arow) * 1024 + ibase + (k & 63) * 2));
                *(uint32_t*)(smem + APH + off) = packhl(h0, h1);
                *(uint32_t*)(smem + APL + off) = packhl(l0, l1);
            }
        }
    }
    FENCE_ASYNC();
    __syncthreads();

    // --- MMA2: D2[128x64] = P * V (SS mode, 3-term split, K=192) ---
    if (wid == 0 && elect_one()) {
        uint64_t dPh = MK_DESC(sb + APH), dPl = MK_DESC(sb + APL);
        uint64_t dVh = MK_DESC(sb + AVH), dVl = MK_DESC(sb + AVL);
        #pragma unroll
        for (int ks = 0; ks < 12; ks++) {
            uint64_t ao = (uint64_t)((ks >> 2) * 1024 + (ks & 3) * 2);
            uint64_t bo = (uint64_t)((ks >> 2) * 512  + (ks & 3) * 2);
            mma_f16_ss(tmem + D2T, dPh + ao, dVh + bo, ID_N64, ks != 0);
        }
        #pragma unroll
        for (int ks = 0; ks < 12; ks++) {
            uint64_t ao = (uint64_t)((ks >> 2) * 1024 + (ks & 3) * 2);
            uint64_t bo = (uint64_t)((ks >> 2) * 512  + (ks & 3) * 2);
            mma_f16_ss(tmem + D2T, dPh + ao, dVl + bo, ID_N64, 1);
        }
        #pragma unroll
        for (int ks = 0; ks < 12; ks++) {
            uint64_t ao = (uint64_t)((ks >> 2) * 1024 + (ks & 3) * 2);
            uint64_t bo = (uint64_t)((ks >> 2) * 512  + (ks & 3) * 2);
            mma_f16_ss(tmem + D2T, dPl + ao, dVh + bo, ID_N64, 1);
        }
        TC_COMMIT(sb + 16);
    }
    mb_wait(sb + 16, 0);
    TC_FENCE_AFTER();

    // --- epilogue: Y = D2 / ssum, written directly as bf16 hi/lo ---
    if (wid < 4) {
        uint32_t r0[32], r1[32];
        tc_ld32(r0, tmem + D2T);
        tc_ld32(r1, tmem + D2T + 32);
        TC_WAIT_LD();
        int m = wid * 32 + lane, h = m >> 4, tqq = m & 15;
        float inv = 1.f / ssum;
        size_t yb = (size_t)(n * TT + t0 + tqq) * HD + h * 64;
        #pragma unroll
        for (int j = 0; j < 16; j++) {
            float v0 = __uint_as_float(r0[2*j])   * inv;
            float v1 = __uint_as_float(r0[2*j+1]) * inv;
            __nv_bfloat16 h0, l0, h1, l1;
            split1(v0, h0, l0); split1(v1, h1, l1);
            *(uint32_t*)&g_Yh[yb + 2*j] = packhl(h0, h1);
            *(uint32_t*)&g_Yl[yb + 2*j] = packhl(l0, l1);
        }
        #pragma unroll
        for (int j = 0; j < 16; j++) {
            float v0 = __uint_as_float(r1[2*j])   * inv;
            float v1 = __uint_as_float(r1[2*j+1]) * inv;
            __nv_bfloat16 h0, l0, h1, l1;
            split1(v0, h0, l0); split1(v1, h1, l1);
            *(uint32_t*)&g_Yh[yb + 32 + 2*j] = packhl(h0, h1);
            *(uint32_t*)&g_Yl[yb + 32 + 2*j] = packhl(l0, l1);
        }
        TC_FENCE_BEFORE();
    }
    __syncthreads();
    if (wid == 0) TC_DEALLOC(tmem, 256);
#endif // TC_OK
}

// ---------------- fallback FFMA GEMMs + SIMT attention (plain pass) --------
__global__ __launch_bounds__(256) void sgemm128_tn(
    const float* __restrict__ X,
    const float* __restrict__ wK, const float* __restrict__ wV,
    const float* __restrict__ wQ)
{
#if !TC_OK
    const float* B; float* C;
    if      (blockIdx.z == 0) { B = wK; C = g_K; }
    else if (blockIdx.z == 1) { B = wV; C = g_V; }
    else                      { B = wQ; C = g_Q; }

    __shared__ float As[8][128];
    __shared__ float Bs[8][128];
    const int tid  = threadIdx.x;
    const int row0 = blockIdx.y * 128;
    const int col0 = blockIdx.x * 128;
    const int lr = tid >> 1, lc = (tid & 1) * 4;
    const int ty = tid >> 4, tx = tid & 15;

    float acc[8][8];
    #pragma unroll
    for (int i = 0; i < 8; i++)
        #pragma unroll
        for (int j = 0; j < 8; j++) acc[i][j] = 0.f;

    const float* Ap = X + (row0 + lr) * DMD + lc;
    const float* Bp = B + (col0 + lr) * DMD + lc;

    for (int k0 = 0; k0 < DMD; k0 += 8) {
        float4 av = *(const float4*)(Ap + k0);
        float4 bv = *(const float4*)(Bp + k0);
        As[lc+0][lr] = av.x; As[lc+1][lr] = av.y; As[lc+2][lr] = av.z; As[lc+3][lr] = av.w;
        Bs[lc+0][lr] = bv.x; Bs[lc+1][lr] = bv.y; Bs[lc+2][lr] = bv.z; Bs[lc+3][lr] = bv.w;
        __syncthreads();
        #pragma unroll
        for (int kk = 0; kk < 8; kk++) {
            float a[8], b[8];
            *(float4*)&a[0] = *(const float4*)&As[kk][ty*8];
            *(float4*)&a[4] = *(const float4*)&As[kk][ty*8+4];
            *(float4*)&b[0] = *(const float4*)&Bs[kk][tx*8];
            *(float4*)&b[4] = *(const float4*)&Bs[kk][tx*8+4];
            #pragma unroll
            for (int i = 0; i < 8; i++)
                #pragma unroll
                for (int j = 0; j < 8; j++)
                    acc[i][j] = fmaf(a[i], b[j], acc[i][j]);
        }
        __syncthreads();
    }

    float* Cp = C + (row0 + ty*8) * HD + col0 + tx*8;
    #pragma unroll
    for (int i = 0; i < 8; i++) {
        *(float4*)(Cp + i*HD)     = make_float4(acc[i][0], acc[i][1], acc[i][2], acc[i][3]);
        *(float4*)(Cp + i*HD + 4) = make_float4(acc[i][4], acc[i][5], acc[i][6], acc[i][7]);
    }
#endif
}

__global__ __launch_bounds__(256) void sgemm128_nn(
    const float* __restrict__ B, float* __restrict__ C)
{
#if !TC_OK
    __shared__ float As[8][128];
    __shared__ float Bs[8][128];
    const int tid  = threadIdx.x;
    const int row0 = blockIdx.y * 128;
    const int col0 = blockIdx.x * 128;
    const int alr = tid >> 1, alc = (tid & 1) * 4;
    const int blr = tid >> 5, blc = (tid & 31) * 4;
    const int ty = tid >> 4, tx = tid & 15;

    float acc[8][8];
    #pragma unroll
    for (int i = 0; i < 8; i++)
        #pragma unroll
        for (int j = 0; j < 8; j++) acc[i][j] = 0.f;

    for (int k0 = 0; k0 < HD; k0 += 8) {
        float4 av = *(const float4*)&g_Y[(row0 + alr)*HD + k0 + alc];
        As[alc+0][alr] = av.x; As[alc+1][alr] = av.y; As[alc+2][alr] = av.z; As[alc+3][alr] = av.w;
        float4 bv = *(const float4*)&B[(k0 + blr)*DMD + col0 + blc];
        *(float4*)&Bs[blr][blc] = bv;
        __syncthreads();
        #pragma unroll
        for (int kk = 0; kk < 8; kk++) {
            float a[8], b[8];
            *(float4*)&a[0] = *(const float4*)&As[kk][ty*8];
            *(float4*)&a[4] = *(const float4*)&As[kk][ty*8+4];
            *(float4*)&b[0] = *(const float4*)&Bs[kk][tx*8];
            *(float4*)&b[4] = *(const float4*)&Bs[kk][tx*8+4];
            #pragma unroll
            for (int i = 0; i < 8; i++)
                #pragma unroll
                for (int j = 0; j < 8; j++)
                    acc[i][j] = fmaf(a[i], b[j], acc[i][j]);
        }
        __syncthreads();
    }

    float* Cp = C + (row0 + ty*8)*DMD + col0 + tx*8;
    #pragma unroll
    for (int i = 0; i < 8; i++) {
        *(float4*)(Cp + i*DMD)     = make_float4(acc[i][0], acc[i][1], acc[i][2], acc[i][3]);
        *(float4*)(Cp + i*DMD + 4) = make_float4(acc[i][4], acc[i][5], acc[i][6], acc[i][7]);
    }
#endif
}

#define TS 16
#define SSPAN 47
#define SROW 65
#define ATTN_SMEM ((2*EE*SSPAN*SROW + 8*64 + 8*128) * 4)

__global__ __launch_bounds__(256) void attn_simt(
    const float* __restrict__ iK, const float* __restrict__ iV)
{
#if !TC_OK
    extern __shared__ float fsm[];
    float* sK = fsm;
    float* sV = sK + EE*SSPAN*SROW;
    float* sQ = sV + EE*SSPAN*SROW;
    float* sA = sQ + 8*64;

    const int n  = blockIdx.y;
    const int t0 = blockIdx.x * TS;
    const int tid = threadIdx.x;

    for (int idx = tid; idx < EE*SSPAN*DD; idx += 256) {
        int d = idx & 63;
        int r = (idx >> 6) % SSPAN;
        int e = idx / (SSPAN*DD);
        int s = t0 - 31 + r;
        float kv, vv;
        if (s >= 0) {
            size_t g = ((size_t)(n*EE + e)*TT + s)*DD + d;
            kv = __bfloat162float(g_sKh[g]) + __bfloat162float(g_sKl[g]);
            vv = __bfloat162float(g_sVh[g]) + __bfloat162float(g_sVl[g]);
        } else {
            int g = (e*LL + (s + 32))*DD + d;
            kv = iK[g]; vv = iV[g];
        }
        sK[(e*SSPAN + r)*SROW + d] = kv;
        sV[(e*SSPAN + r)*SROW + d] = vv;
    }
    __syncthreads();

    const int w = tid >> 5, lane = tid & 31;
    for (int task = w; task < TS*HH; task += 8) {
        int tq = task & (TS - 1);
        int h  = task >> 4;
        int nt = n*TT + t0 + tq;

        sQ[w*64 + lane]      = g_Q[nt*HD + h*64 + lane]      * 0.125f;
        sQ[w*64 + lane + 32] = g_Q[nt*HD + h*64 + lane + 32] * 0.125f;
        __syncwarp();

        float sc[4] = {0.f,0.f,0.f,0.f};
        #pragma unroll 4
        for (int d = 0; d < 64; d++) {
            float q = sQ[w*64 + d];
            #pragma unroll
            for (int e = 0; e < EE; e++)
                sc[e] = fmaf(q, sK[(e*SSPAN + tq + lane)*SROW + d], sc[e]);
        }
        float mx = fmaxf(fmaxf(sc[0], sc[1]), fmaxf(sc[2], sc[3]));
        #pragma unroll
        for (int o = 16; o; o >>= 1) mx = fmaxf(mx, __shfl_xor_sync(0xffffffffu, mx, o));
        float ssum = 0.f;
        #pragma unroll
        for (int e = 0; e < EE; e++) { sc[e] = __expf(sc[e] - mx); ssum += sc[e]; }
        #pragma unroll
        for (int o = 16; o; o >>= 1) ssum += __shfl_xor_sync(0xffffffffu, ssum, o);
        float inv = 1.f / ssum;
        #pragma unroll
        for (int e = 0; e < EE; e++) sA[w*128 + e*32 + lane] = sc[e] * inv;
        __syncwarp();

        float o0 = 0.f, o1 = 0.f;
        #pragma unroll 2
        for (int e = 0; e < EE; e++)
            for (int j = 0; j < LL; j++) {
                float a = sA[w*128 + e*32 + j];
                int base = (e*SSPAN + tq + j)*SROW;
                o0 = fmaf(a, sV[base + lane],      o0);
                o1 = fmaf(a, sV[base + lane + 32], o1);
            }
        g_Y[nt*HD + h*64 + lane]      = o0;
        g_Y[nt*HD + h*64 + lane + 32] = o1;
        __syncwarp();
    }
#endif
}

// ---------------- G projection fallback (plain pass only): raw scores ------
__global__ __launch_bounds__(256) void gproj_fb(
    const float* __restrict__ X, const float* __restrict__ wG)
{
#if !TC_OK
    __shared__ float As[32][32];
    __shared__ float Bs[32][33];
    const int tid  = threadIdx.x;
    const int row0 = blockIdx.x * 32;
    const int tx = tid & 31, ty = tid >> 5;
    const int lr = tid >> 3, lc = (tid & 7) * 4;

    float acc[4] = {0.f, 0.f, 0.f, 0.f};
    for (int k0 = 0; k0 < DMD; k0 += 32) {
        float4 xv = *(const float4*)&X[(row0 + lr) * DMD + k0 + lc];
        *(float4*)&As[lr][lc] = xv;
        float4 wv = *(const float4*)&wG[lr * DMD + k0 + lc];
        Bs[lr][lc] = wv.x; Bs[lr][lc+1] = wv.y; Bs[lr][lc+2] = wv.z; Bs[lr][lc+3] = wv.w;
        __syncthreads();
        #pragma unroll
        for (int kk = 0; kk < 32; kk++) {
            float b = Bs[tx][kk];
            #pragma unroll
            for (int i = 0; i < 4; i++)
                acc[i] = fmaf(As[ty*4+i][kk], b, acc[i]);
        }
        __syncthreads();
    }
    #pragma unroll
    for (int i = 0; i < 4; i++)
        g_Gpre[(size_t)(row0 + ty*4 + i) * HD + tx] = acc[i];
#endif
}

// ---------------- gating mix + A (cooperative sigmoid) ---------------------
__global__ __launch_bounds__(256) void gate_kernel(const float* __restrict__ bG)
{
    __shared__ float sg[4][32];           // sigmoid gate values per token
    const int tid = threadIdx.x;
    const int nt0 = blockIdx.x * 4;

    if (tid < 128) {                      // one sigmoid per thread
        int tok = tid >> 5, j = tid & 31;
        float raw = g_Gpre[(size_t)(nt0 + tok) * HD + j] + bG[j];
        sg[tok][j] = 1.f / (1.f + __expf(-raw));
    }
    __syncthreads();

    if (tid < 16) {                       // A = 1 - sum_h g
        int tok = tid >> 2, e = tid & 3;
        float s = 0.f;
        #pragma unroll
        for (int h = 0; h < HH; h++) s += sg[tok][h*4 + e];
        int nt = nt0 + tok;
        int n = nt >> 11, t = nt & (TT - 1);
        g_A[(n*EE + e)*TT + t] = 1.f - s;
    }

    const int tok = tid >> 6;
    const int nt  = nt0 + tok;
    const int d   = tid & 63;
    const int n   = nt >> 11;
    const int t   = nt & (TT - 1);

    float sKv[4] = {0.f,0.f,0.f,0.f}, sVv[4] = {0.f,0.f,0.f,0.f};
    #pragma unroll
    for (int h = 0; h < HH; h++) {
        float kv = g_K[nt*HD + h*64 + d];
        float vv = g_V[nt*HD + h*64 + d];
        #pragma unroll
        for (int e = 0; e < EE; e++) {
            float g = sg[tok][h*4 + e];   // LDS broadcast within warp
            sKv[e] = fmaf(g, kv, sKv[e]);
            sVv[e] = fmaf(g, vv, sVv[e]);
        }
    }
    #pragma unroll
    for (int e = 0; e < EE; e++) {
        int o = ((n*EE + e)*TT + t) * DD + d;
        g_gK[o] = sKv[e];
        g_gV[o] = sVv[e];
    }
}

// ---------------- stride-32 recurrence (pipelined loads) -------------------
__global__ __launch_bounds__(256) void scan_kernel(
    const float* __restrict__ iK, const float* __restrict__ iV)
{
    const int idx = blockIdx.x * 256 + threadIdx.x;   // 32768 threads
    const int d = idx & 63;
    const int p = (idx >> 6) & 31;
    const int e = (idx >> 11) & 3;
    const int n = (idx >> 13) & 1;
    const int kv = idx >> 14;

    const float* init = kv ? iV : iK;
    const float* gsrc = kv ? g_gV : g_gK;
    __nv_bfloat16* dh = kv ? g_sVh : g_sKh;
    __nv_bfloat16* dl = kv ? g_sVl : g_sKl;

    float pk = init[(e*LL + p)*DD + d];
    const int rowbase = (n*EE + e) * TT;

    float aA[8], gA[8], aB[8], gB[8];
#define LOADG(av, gv, grp)                                          \
    _Pragma("unroll")                                               \
    for (int i = 0; i < 8; i++) {                                   \
        int t = ((grp)*8 + i)*LL + p;                               \
        av[i] = __ldg(&g_A[rowbase + t]);                           \
        gv[i] = __ldg(&gsrc[(rowbase + t)*DD + d]);                 \
    }
    LOADG(aA, gA, 0);
    #pragma unroll
    for (int m = 0; m < 8; m++) {        // 8 groups of 8 steps
        if (m + 1 < 8) { LOADG(aB, gB, m + 1); }
        #pragma unroll
        for (int i = 0; i < 8; i++) {
            pk = fmaf(aA[i], pk, gA[i]);
            __nv_bfloat16 h, l;
            split1(pk, h, l);
            int o = (rowbase + (m*8 + i)*LL + p)*DD + d;
            dh[o] = h; dl[o] = l;
        }
        #pragma unroll
        for (int i = 0; i < 8; i++) { aA[i] = aB[i]; gA[i] = gB[i]; }
    }
#undef LOADG
}

// ---------------- launcher -------------------------------------------------
extern "C" void kernel_launch(void* const* d_in, const int* in_sizes, int n_in,
                              void* d_out, int out_size)
{
    const float* X  = (const float*)d_in[0];
    const float* wG = (const float*)d_in[1];
    const float* bG = (const float*)d_in[2];
    const float* wK = (const float*)d_in[3];
    const float* wV = (const float*)d_in[4];
    const float* wQ = (const float*)d_in[5];
    const float* wO = (const float*)d_in[6];
    const float* iK = (const float*)d_in[7];
    const float* iV = (const float*)d_in[8];
    float* out = (float*)d_out;
    (void)in_sizes; (void)n_in; (void)out_size;

    void *pXh, *pXl, *pWh, *pWl, *pWOh, *pWOl, *pYh, *pYl, *pK, *pV, *pQ, *pGp;
    cudaGetSymbolAddress(&pXh, g_Xh);   cudaGetSymbolAddress(&pXl, g_Xl);
    cudaGetSymbolAddress(&pWh, g_Wh);   cudaGetSymbolAddress(&pWl, g_Wl);
    cudaGetSymbolAddress(&pWOh, g_WOh); cudaGetSymbolAddress(&pWOl, g_WOl);
    cudaGetSymbolAddress(&pYh, g_Yh);   cudaGetSymbolAddress(&pYl, g_Yl);
    cudaGetSymbolAddress(&pK, g_K); cudaGetSymbolAddress(&pV, g_V);
    cudaGetSymbolAddress(&pQ, g_Q); cudaGetSymbolAddress(&pGp, g_Gpre);

    // On sm_10x the tcgen05 cubin is loaded; fallback launches are dead weight.
    int dev = 0, ccmaj = 0;
    cudaGetDevice(&dev);
    cudaDeviceGetAttribute(&ccmaj, cudaDevAttrComputeCapabilityMajor, dev);
    const bool tc = (ccmaj == 10);

    cudaFuncSetAttribute(attn_simt,
                         cudaFuncAttributeMaxDynamicSharedMemorySize, ATTN_SMEM);
    cudaFuncSetAttribute(attn_tc,
                         cudaFuncAttributeMaxDynamicSharedMemorySize, ATC_SMEM);
    cudaFuncSetAttribute(tc_gemm,
                         cudaFuncAttributeMaxDynamicSharedMemorySize, TC_SMEM);

    // side stream for the Q-projection (overlaps gate+scan); created fresh
    // per call (kernel_launch runs only for correctness + capture)
    cudaStream_t s2;
    cudaEvent_t evFork, evJoin;
    cudaStreamCreateWithFlags(&s2, cudaStreamNonBlocking);
    cudaEventCreateWithFlags(&evFork, cudaEventDisableTiming);
    cudaEventCreateWithFlags(&evJoin, cudaEventDisableTiming);

    // split X + wK/wV/wQ + wG (+ zero pad) + wO transpose in ONE launch
    split_all<<<6272, 256>>>(X, wK, wV, wQ, wG, wO);

    // fork: projQ (cols 8..11) on s2, concurrent with projKV/projG+gate+scan
    cudaEventRecord(evFork, 0);
    cudaStreamWaitEvent(s2, evFork, 0);
    tc_gemm<<<dim3(4, 32), 256, TC_SMEM, s2>>>(
        (const __nv_bfloat16*)pXh, (const __nv_bfloat16*)pXl,
        (const __nv_bfloat16*)pWh, (const __nv_bfloat16*)pWl,
        DMD, (float*)pK, (float*)pV, (float*)pQ, (float*)pGp, HD, 8);
    cudaEventRecord(evJoin, s2);

    // main stream: K/V (cols 0..7) + G (col 12) projections
    tc_gemm<<<dim3(8, 32), 256, TC_SMEM>>>(
        (const __nv_bfloat16*)pXh, (const __nv_bfloat16*)pXl,
        (const __nv_bfloat16*)pWh, (const __nv_bfloat16*)pWl,
        DMD, (float*)pK, (float*)pV, (float*)pQ, (float*)pGp, HD, 0);
    tc_gemm<<<dim3(1, 32), 256, TC_SMEM>>>(
        (const __nv_bfloat16*)pXh, (const __nv_bfloat16*)pXl,
        (const __nv_bfloat16*)pWh, (const __nv_bfloat16*)pWl,
        DMD, (float*)pK, (float*)pV, (float*)pQ, (float*)pGp, HD, 12);
    if (!tc) {
        sgemm128_tn<<<dim3(4, 32, 3), 256>>>(X, wK, wV, wQ);
        gproj_fb<<<128, 256>>>(X, wG);
    }

    gate_kernel<<<NT/4, 256>>>(bG);
    scan_kernel<<<128, 256>>>(iK, iV);

    // join: attn needs Q (s2) + scan outputs (main)
    cudaStreamWaitEvent(0, evJoin, 0);

    attn_tc<<<dim3(TT/16, NB), 256, ATC_SMEM>>>(iK, iV);
    if (!tc)
        attn_simt<<<dim3(TT/TS, NB), 256, ATTN_SMEM>>>(iK, iV);

    // output projection out = Y @ wO (attn_tc wrote Yh/Yl directly)
    tc_gemm<<<dim3(8, 32), 256, TC_SMEM>>>(
        (const __nv_bfloat16*)pYh, (const __nv_bfloat16*)pYl,
        (const __nv_bfloat16*)pWOh, (const __nv_bfloat16*)pWOl,
        HD, out, out, out, out, DMD, 0);
    if (!tc)
        sgemm128_nn<<<dim3(8, 32), 256>>>(wO, out);
}

// round 16
// speedup vs baseline: 1.1377x; 1.1377x over previous
#include <cuda_runtime.h>
#include <cuda_bf16.h>
#include <cstdint>

// Arch gate: tcgen05 only exists in the sm_103a/sm_100a-specific passes.
#if !defined(__CUDA_ARCH__) || defined(__CUDA_ARCH_FEAT_SM103_ALL) || defined(__CUDA_ARCH_FEAT_SM100_ALL)
#define TC_OK 1
#else
#define TC_OK 0
#endif

// Problem constants
#define NB 2
#define TT 2048
#define DMD 1024
#define HH 8
#define EE 4
#define LL 32
#define DD 64
#define NT (NB*TT)      // 4096
#define HD (HH*DD)      // 512

// ---------------- scratch (device globals; no allocation allowed) ----------
__device__ float g_K[NT*HD];
__device__ float g_V[NT*HD];
__device__ float g_Q[NT*HD];
__device__ float g_Gpre[NT*HD];     // raw G scores in cols [0,32) of each 512-row
__device__ float g_A[NB*EE*TT];
__device__ float g_gK[NB*EE*TT*DD];
__device__ float g_gV[NB*EE*TT*DD];
__device__ float g_Y[NT*HD];

// scan outputs as bf16 hi/lo (consumed by tensor attention)
__device__ __nv_bfloat16 g_sKh[NB*EE*TT*DD], g_sKl[NB*EE*TT*DD];
__device__ __nv_bfloat16 g_sVh[NB*EE*TT*DD], g_sVl[NB*EE*TT*DD];

// bf16 split operands for tensor-core GEMMs
// W layout: [wK 512 | wV 512 | wQ 512 | wG 32 + zero-pad 96] rows of 1024
__device__ __nv_bfloat16 g_Xh[NT*DMD], g_Xl[NT*DMD];
__device__ __nv_bfloat16 g_Wh[(3*HD + 128)*DMD], g_Wl[(3*HD + 128)*DMD];
__device__ __nv_bfloat16 g_WOh[DMD*HD], g_WOl[DMD*HD];
__device__ __nv_bfloat16 g_Yh[NT*HD], g_Yl[NT*HD];

// ---------------- PTX helpers ----------------------------------------------
__device__ __forceinline__ uint32_t smem_u32(const void* p) {
    uint32_t a;
    asm("{ .reg .u64 t; cvta.to.shared.u64 t, %1; cvt.u32.u64 %0, t; }"
        : "=r"(a) : "l"(p));
    return a;
}
__device__ __forceinline__ uint32_t elect_one() {
    uint32_t pred;
    asm volatile("{ .reg .pred p; elect.sync _|p, 0xFFFFFFFF; selp.b32 %0, 1, 0, p; }"
                 : "=r"(pred));
    return pred;
}
#define MB_INIT(mb, cnt) \
    asm volatile("mbarrier.init.shared.b64 [%0], %1;" :: "r"(mb), "r"(cnt) : "memory")
#define FENCE_ASYNC()     asm volatile("fence.proxy.async.shared::cta;" ::: "memory")
#define CPA16(dst, src) \
    asm volatile("cp.async.cg.shared.global [%0], [%1], 16;" :: "r"(dst), "l"(src) : "memory")
#define CPA_COMMIT() asm volatile("cp.async.commit_group;" ::: "memory")
#define CPA_WAIT0()  asm volatile("cp.async.wait_group 0;" ::: "memory")

__device__ __forceinline__ void mb_wait(uint32_t mb, uint32_t parity) {
    uint32_t done;
    asm volatile("{ .reg .pred p; mbarrier.try_wait.parity.acquire.cta.shared::cta.b64 p, [%1], %2;"
                 " selp.b32 %0, 1, 0, p; }" : "=r"(done) : "r"(mb), "r"(parity) : "memory");
    if (!done) {
        asm volatile("{ .reg .pred P1; WL%=:"
                     " mbarrier.try_wait.parity.acquire.cta.shared::cta.b64 P1, [%0], %1, 0x989680;"
                     " @P1 bra.uni WD%=; bra.uni WL%=; WD%=: }"
                     :: "r"(mb), "r"(parity) : "memory");
    }
}

#if TC_OK
#define TC_ALLOC(sm, n) \
    asm volatile("tcgen05.alloc.cta_group::1.sync.aligned.shared::cta.b32 [%0], %1;" \
                 :: "r"(sm), "r"(n) : "memory")
#define TC_DEALLOC(tm, n) \
    asm volatile("tcgen05.dealloc.cta_group::1.sync.aligned.b32 %0, %1;" :: "r"(tm), "r"(n))
#define TC_RELINQ() \
    asm volatile("tcgen05.relinquish_alloc_permit.cta_group::1.sync.aligned;")
#define TC_COMMIT(mb) \
    asm volatile("tcgen05.commit.cta_group::1.mbarrier::arrive::one.shared::cluster.b64 [%0];" \
                 :: "r"(mb) : "memory")
#define TC_FENCE_AFTER()  asm volatile("tcgen05.fence::after_thread_sync;" ::: "memory")
#define TC_FENCE_BEFORE() asm volatile("tcgen05.fence::before_thread_sync;" ::: "memory")
#define TC_WAIT_LD()      asm volatile("tcgen05.wait::ld.sync.aligned;" ::: "memory")

__device__ __forceinline__ void mma_f16_ss(uint32_t d, uint64_t ad, uint64_t bd,
                                           uint32_t idesc, uint32_t en) {
    asm volatile("{ .reg .pred p; setp.ne.u32 p, %5, 0;"
                 " tcgen05.mma.cta_group::1.kind::f16 [%0], %1, %2, %3, {%4,%4,%4,%4}, p; }"
                 :: "r"(d), "l"(ad), "l"(bd), "r"(idesc), "r"(0u), "r"(en) : "memory");
}
__device__ __forceinline__ void tc_ld32(uint32_t* r, uint32_t addr) {
    asm volatile("tcgen05.ld.sync.aligned.32x32b.x32.b32 "
        "{%0,%1,%2,%3,%4,%5,%6,%7,%8,%9,%10,%11,%12,%13,%14,%15,"
        "%16,%17,%18,%19,%20,%21,%22,%23,%24,%25,%26,%27,%28,%29,%30,%31}, [%32];"
        : "=r"(r[0]),"=r"(r[1]),"=r"(r[2]),"=r"(r[3]),"=r"(r[4]),"=r"(r[5]),"=r"(r[6]),"=r"(r[7]),
          "=r"(r[8]),"=r"(r[9]),"=r"(r[10]),"=r"(r[11]),"=r"(r[12]),"=r"(r[13]),"=r"(r[14]),"=r"(r[15]),
          "=r"(r[16]),"=r"(r[17]),"=r"(r[18]),"=r"(r[19]),"=r"(r[20]),"=r"(r[21]),"=r"(r[22]),"=r"(r[23]),
          "=r"(r[24]),"=r"(r[25]),"=r"(r[26]),"=r"(r[27]),"=r"(r[28]),"=r"(r[29]),"=r"(r[30]),"=r"(r[31])
        : "r"(addr));
}
#endif // TC_OK

static constexpr uint64_t DESC_BASE_SW128 =
    (uint64_t(2) << 61) | (uint64_t(1) << 46) | (uint64_t(64) << 32) | (uint64_t(1) << 16);
#define MK_DESC(a) (DESC_BASE_SW128 | ((uint64_t)((a) >> 4) & 0x3FFF))
#define SWZ(o) ((o) ^ (((o) >> 3) & 0x70))

// idesc: F32 accum, BF16 a/b, M=128; N field = (N/8)<<17
#define ID_N128 0x8200490u
#define ID_N192 0x8300490u
#define ID_N64  0x8100490u

__device__ __forceinline__ void split1(float x, __nv_bfloat16& h, __nv_bfloat16& l) {
    h = __float2bfloat16(x);
    l = __float2bfloat16(x - __bfloat162float(h));
}
__device__ __forceinline__ uint32_t packhl(__nv_bfloat16 a, __nv_bfloat16 b) {
    __nv_bfloat162 t(a, b);
    return *(uint32_t*)&t;
}

// ---------------- split kernels --------------------------------------------
// One launch splits X, wK/wV/wQ, wG, zero-pads the wG tile, and
// transpose-splits wO.
__global__ __launch_bounds__(256) void split_all(
    const float* __restrict__ X,
    const float* __restrict__ wK, const float* __restrict__ wV,
    const float* __restrict__ wQ, const float* __restrict__ wG,
    const float* __restrict__ wO)
{
    __shared__ float t[32][33];
    int b = blockIdx.x;
    if (b >= 5760) {                      // wO transpose-split
        int j = b - 5760;
        int n0 = (j & 31) * 32, k0 = (j >> 5) * 32;
        int tx = threadIdx.x & 31, ty = threadIdx.x >> 5;
        #pragma unroll
        for (int jj = 0; jj < 32; jj += 8)
            t[ty + jj][tx] = wO[(k0 + ty + jj) * DMD + n0 + tx];
        __syncthreads();
        #pragma unroll
        for (int jj = 0; jj < 32; jj += 8) {
            __nv_bfloat16 h, l;
            split1(t[tx][ty + jj], h, l);
            g_WOh[(n0 + ty + jj) * HD + k0 + tx] = h;
            g_WOl[(n0 + ty + jj) * HD + k0 + tx] = l;
        }
        return;
    }
    if (b >= 5664) {                      // zero-pad
        int i = ((b - 5664) * 256 + threadIdx.x) * 4;
        size_t o = (size_t)(3*HD + 32) * DMD + i;
        *(uint64_t*)(g_Wh + o) = 0ull;
        *(uint64_t*)(g_Wl + o) = 0ull;
        return;
    }
    const float* s;
    __nv_bfloat16 *h, *l;
    int i;
    if (b < 4096) {
        s = X; h = g_Xh; l = g_Xl;
        i = b * 256 + threadIdx.x;
    } else if (b < 5632) {
        int j = b - 4096;
        int mat = j >> 9;
        s = (mat == 0) ? wK : (mat == 1) ? wV : wQ;
        h = g_Wh + (size_t)mat * HD * DMD;
        l = g_Wl + (size_t)mat * HD * DMD;
        i = (j & 511) * 256 + threadIdx.x;
    } else {                              // wG: 32 rows x 1024 = 8192 float4
        s = wG;
        h = g_Wh + (size_t)3 * HD * DMD;
        l = g_Wl + (size_t)3 * HD * DMD;
        i = (b - 5632) * 256 + threadIdx.x;
    }
    i <<= 2;
    float4 v = *(const float4*)(s + i);
    float xs[4] = {v.x, v.y, v.z, v.w};
    __nv_bfloat16 hh[4], ll[4];
    #pragma unroll
    for (int j = 0; j < 4; j++) split1(xs[j], hh[j], ll[j]);
    ((__nv_bfloat162*)(h + i))[0] = __nv_bfloat162(hh[0], hh[1]);
    ((__nv_bfloat162*)(h + i))[1] = __nv_bfloat162(hh[2], hh[3]);
    ((__nv_bfloat162*)(l + i))[0] = __nv_bfloat162(ll[0], ll[1]);
    ((__nv_bfloat162*)(l + i))[1] = __nv_bfloat162(ll[2], ll[3]);
}

// ---------------- tcgen05 GEMM (sm_103a pass only) -------------------------
// PROVEN BEST: 128x128 tiles, single 64KB stage, occ-3; 8 warps for fast
// cp.async issue. MMA from warp 0, epilogue warps 0-3. Fused 13-col launch.
#define TC_SMEM (1024 + 65536)

__global__ __launch_bounds__(256, 3) void tc_gemm(
    const __nv_bfloat16* __restrict__ Ah, const __nv_bfloat16* __restrict__ Al,
    const __nv_bfloat16* __restrict__ Bh, const __nv_bfloat16* __restrict__ Bl,
    int K, float* C0, float* C1, float* C2, float* C3, int colmat)
{
#if TC_OK
    extern __shared__ char smem[];
    uint32_t sb = smem_u32(smem);
    const int tid = threadIdx.x, wid = tid >> 5, lid = tid & 31;
    const int row0 = blockIdx.y * 128, col0 = blockIdx.x * 128;

    if (wid == 0) { TC_ALLOC(sb, 128); TC_RELINQ(); }
    __syncthreads();
    uint32_t tmem;
    asm volatile("ld.shared.b32 %0, [%1];" : "=r"(tmem) : "r"(sb));
    if (tid == 0) MB_INIT(sb + 8, 1);
    __syncthreads();

    const __nv_bfloat16* src[4] = { Ah + (size_t)row0 * K, Al + (size_t)row0 * K,
                                    Bh + (size_t)col0 * K, Bl + (size_t)col0 * K };
    const int NC = K >> 6;
    uint32_t stb = sb + 1024;
    uint64_t dA[2] = { MK_DESC(stb), MK_DESC(stb + 16384) };
    uint64_t dB[2] = { MK_DESC(stb + 32768), MK_DESC(stb + 49152) };

    int ph = 0;
    for (int c = 0; c < NC; c++) {
        if (c > 0) { mb_wait(sb + 8, ph); ph ^= 1; }
        int kof = c * 64;
        #pragma unroll
        for (int u = tid; u < 4096; u += 256) {
            int buf = u >> 10, wi = u & 1023;
            int r = wi >> 3, cb = wi & 7;
            uint32_t off = SWZ((uint32_t)(r * 128 + cb * 16));
            CPA16(stb + buf * 16384 + off, src[buf] + (size_t)r * K + kof + cb * 8);
        }
        CPA_COMMIT();
        CPA_WAIT0();
        FENCE_ASYNC();
        __syncthreads();
        if (wid == 0 && elect_one()) {
            #pragma unroll
            for (int ks = 0; ks < 4; ks++)
                mma_f16_ss(tmem, dA[0] + ks * 2, dB[0] + ks * 2, ID_N128, !(c == 0 && ks == 0));
            #pragma unroll
            for (int ks = 0; ks < 4; ks++)
                mma_f16_ss(tmem, dA[0] + ks * 2, dB[1] + ks * 2, ID_N128, 1);
            #pragma unroll
            for (int ks = 0; ks < 4; ks++)
                mma_f16_ss(tmem, dA[1] + ks * 2, dB[0] + ks * 2, ID_N128, 1);
            TC_COMMIT(sb + 8);
        }
        __syncthreads();
    }
    mb_wait(sb + 8, ph);
    TC_FENCE_AFTER();

    if (wid < 4) {
        int mat = col0 / colmat;
        float* C = (mat == 0) ? C0 : (mat == 1) ? C1 : (mat == 2) ? C2 : C3;
        int lc0 = col0 - mat * colmat;
        float* dst = C + (size_t)(row0 + wid * 32 + lid) * colmat + lc0;
        #pragma unroll
        for (int pass = 0; pass < 4; pass++) {
            uint32_t r[32];
            tc_ld32(r, tmem + pass * 32);
            TC_WAIT_LD();
            #pragma unroll
            for (int j = 0; j < 8; j++)
                *(float4*)&dst[pass * 32 + j * 4] =
                    make_float4(__uint_as_float(r[j*4]),   __uint_as_float(r[j*4+1]),
                                __uint_as_float(r[j*4+2]), __uint_as_float(r[j*4+3]));
        }
        TC_FENCE_BEFORE();
    }
    __syncthreads();
    if (wid == 0) TC_DEALLOC(tmem, 128);
#endif // TC_OK
}

// ---------------- tensor-core windowed attention (sm_103a pass) ------------
#define D2T 192              // TMEM col offset of AV accumulator
#define AVH 1024
#define AVL (AVH + 24576)    // 25600
#define AQH 50176
#define AQL (AQH + 16384)    // 66560
#define AKH (AQL + 16384)    // 82944
#define AKL (AKH + 24576)    // 107520
#define APH 50176            // reuse Q/K region after MMA1
#define APL (APH + 49152)    // 99328
#define ATC_SMEM 148480

__global__ __launch_bounds__(256) void attn_tc(
    const float* __restrict__ iK, const float* __restrict__ iV)
{
#if TC_OK
    extern __shared__ char smem[];
    uint32_t sb = smem_u32(smem);
    const int tid = threadIdx.x, wid = tid >> 5, lane = tid & 31;
    const int n = blockIdx.y, t0 = blockIdx.x * 16;

    if (wid == 0) { TC_ALLOC(sb, 256); TC_RELINQ(); }
    __syncthreads();
    uint32_t tmem;
    asm volatile("ld.shared.b32 %0, [%1];" : "=r"(tmem) : "r"(sb));
    if (tid == 0) { MB_INIT(sb + 8, 1); MB_INIT(sb + 16, 1); }

    // --- stage Q (scaled by 1/8, hi/lo split), rows m = h*16+tq, SW128 ---
    for (int idx = tid; idx < 128 * 32; idx += 256) {
        int m = idx >> 5, d2 = (idx & 31) * 2;
        int h = m >> 4, tq = m & 15;
        const float* qp = &g_Q[(size_t)(n * TT + t0 + tq) * HD + h * 64 + d2];
        float x0 = qp[0] * 0.125f, x1 = qp[1] * 0.125f;
        __nv_bfloat16 h0, l0, h1, l1;
        split1(x0, h0, l0); split1(x1, h1, l1);
        uint32_t off = SWZ((uint32_t)(m * 128 + d2 * 2));
        *(uint32_t*)(smem + AQH + off) = packhl(h0, h1);
        *(uint32_t*)(smem + AQL + off) = packhl(l0, l1);
    }
    // --- stage K rows (key rr = e*48+r), 16B granules, SW128 K-major ---
    for (int idx = tid; idx < 192 * 8; idx += 256) {
        int rr = idx >> 3, gc = idx & 7;
        int e = rr / 48, r = rr - e * 48;
        int s = t0 - 31 + r;
        uint32_t off = SWZ((uint32_t)(rr * 128 + gc * 16));
        uint4 vh, vl;
        if (r == 47) {
            vh = make_uint4(0, 0, 0, 0); vl = vh;
        } else if (s >= 0) {
            size_t g = ((size_t)(n * EE + e) * TT + s) * 64 + gc * 8;
            vh = *(const uint4*)&g_sKh[g];
            vl = *(const uint4*)&g_sKl[g];
        } else {
            const float* ip = &iK[(size_t)(e * 32 + (s + 32)) * 64 + gc * 8];
            float4 f0 = *(const float4*)ip, f1 = *(const float4*)(ip + 4);
            float fx[8] = {f0.x, f0.y, f0.z, f0.w, f1.x, f1.y, f1.z, f1.w};
            uint32_t hw[4], lw[4];
            #pragma unroll
            for (int j = 0; j < 4; j++) {
                __nv_bfloat16 a, b, c2, d2b;
                split1(fx[2*j], a, b); split1(fx[2*j+1], c2, d2b);
                hw[j] = packhl(a, c2);
                lw[j] = packhl(b, d2b);
            }
            vh = make_uint4(hw[0], hw[1], hw[2], hw[3]);
            vl = make_uint4(lw[0], lw[1], lw[2], lw[3]);
        }
        *(uint4*)(smem + AKH + off) = vh;
        *(uint4*)(smem + AKL + off) = vl;
    }
    // --- stage V as B-operand blocked atoms: [64 dims] x [192 keys] ---
    for (int idx = tid; idx < 192 * 64; idx += 256) {
        int d = idx & 63, rr = idx >> 6;
        int e = rr / 48, r = rr - e * 48;
        int s = t0 - 31 + r;
        int atom = (d >> 3) + (rr >> 6) * 8;
        uint32_t off = SWZ((uint32_t)(atom * 1024 + (d & 7) * 128 + (rr & 63) * 2));
        __nv_bfloat16 vh, vl;
        if (r == 47) {
            vh = __float2bfloat16(0.f); vl = vh;
        } else if (s >= 0) {
            size_t g = ((size_t)(n * EE + e) * TT + s) * 64 + d;
            vh = g_sVh[g]; vl = g_sVl[g];
        } else {
            split1(iV[(size_t)(e * 32 + (s + 32)) * 64 + d], vh, vl);
        }
        *(__nv_bfloat16*)(smem + AVH + off) = vh;
        *(__nv_bfloat16*)(smem + AVL + off) = vl;
    }
    FENCE_ASYNC();
    __syncthreads();

    // --- MMA1: scores D1[128x192] = Q * K^T (3-term split) ---
    if (wid == 0 && elect_one()) {
        uint64_t dQh = MK_DESC(sb + AQH), dQl = MK_DESC(sb + AQL);
        uint64_t dKh = MK_DESC(sb + AKH), dKl = MK_DESC(sb + AKL);
        #pragma unroll
        for (int ks = 0; ks < 4; ks++)
            mma_f16_ss(tmem, dQh + ks * 2, dKh + ks * 2, ID_N192, ks != 0);
        #pragma unroll
        for (int ks = 0; ks < 4; ks++)
            mma_f16_ss(tmem, dQh + ks * 2, dKl + ks * 2, ID_N192, 1);
        #pragma unroll
        for (int ks = 0; ks < 4; ks++)
            mma_f16_ss(tmem, dQl + ks * 2, dKh + ks * 2, ID_N192, 1);
        TC_COMMIT(sb + 8);
    }
    mb_wait(sb + 8, 0);
    TC_FENCE_AFTER();

    // --- softmax: pass 1 row-max, pass 2 exp(s-mx) -> P (hi/lo) in SMEM ---
    float ssum = 0.f;
    if (wid < 4) {
        const int m = wid * 32 + lane;
        const int tq = m & 15;
        float mx = -1e30f;
        #pragma unroll
        for (int cc = 0; cc < 6; cc++) {
            uint32_t r32[32];
            tc_ld32(r32, tmem + cc * 32);
            TC_WAIT_LD();
            #pragma unroll
            for (int j = 0; j < 32; j++) {
                int c = cc * 32 + j;
                int r = c % 48;
                float sv = __uint_as_float(r32[j]);
                if (((unsigned)(r - tq)) < 32u) mx = fmaxf(mx, sv);
            }
        }
        const int arow = m >> 3;
        const uint32_t ibase = (uint32_t)((m & 7) * 128);
        #pragma unroll
        for (int cc = 0; cc < 6; cc++) {
            uint32_t r32[32];
            tc_ld32(r32, tmem + cc * 32);
            TC_WAIT_LD();
            #pragma unroll
            for (int jp = 0; jp < 16; jp++) {
                int k = cc * 32 + jp * 2;
                float ev0, ev1;
                {
                    int r = k % 48;
                    float sv = __uint_as_float(r32[jp * 2]);
                    ev0 = (((unsigned)(r - tq)) < 32u) ? __expf(sv - mx) : 0.f;
                }
                {
                    int r = (k + 1) % 48;
                    float sv = __uint_as_float(r32[jp * 2 + 1]);
                    ev1 = (((unsigned)(r - tq)) < 32u) ? __expf(sv - mx) : 0.f;
                }
                ssum += ev0 + ev1;
                __nv_bfloat16 h0, l0, h1, l1;
                split1(ev0, h0, l0); split1(ev1, h1, l1);
                uint32_t off = SWZ((uint32_t)(((k >> 6) * 16 + arow) * 1024 + ibase + (k & 63) * 2));
                *(uint32_t*)(smem + APH + off) = packhl(h0, h1);
                *(uint32_t*)(smem + APL + off) = packhl(l0, l1);
            }
        }
    }
    FENCE_ASYNC();
    __syncthreads();

    // --- MMA2: D2[128x64] = P * V (SS mode, 3-term split, K=192) ---
    if (wid == 0 && elect_one()) {
        uint64_t dPh = MK_DESC(sb + APH), dPl = MK_DESC(sb + APL);
        uint64_t dVh = MK_DESC(sb + AVH), dVl = MK_DESC(sb + AVL);
        #pragma unroll
        for (int ks = 0; ks < 12; ks++) {
            uint64_t ao = (uint64_t)((ks >> 2) * 1024 + (ks & 3) * 2);
            uint64_t bo = (uint64_t)((ks >> 2) * 512  + (ks & 3) * 2);
            mma_f16_ss(tmem + D2T, dPh + ao, dVh + bo, ID_N64, ks != 0);
        }
        #pragma unroll
        for (int ks = 0; ks < 12; ks++) {
            uint64_t ao = (uint64_t)((ks >> 2) * 1024 + (ks & 3) * 2);
            uint64_t bo = (uint64_t)((ks >> 2) * 512  + (ks & 3) * 2);
            mma_f16_ss(tmem + D2T, dPh + ao, dVl + bo, ID_N64, 1);
        }
        #pragma unroll
        for (int ks = 0; ks < 12; ks++) {
            uint64_t ao = (uint64_t)((ks >> 2) * 1024 + (ks & 3) * 2);
            uint64_t bo = (uint64_t)((ks >> 2) * 512  + (ks & 3) * 2);
            mma_f16_ss(tmem + D2T, dPl + ao, dVh + bo, ID_N64, 1);
        }
        TC_COMMIT(sb + 16);
    }
    mb_wait(sb + 16, 0);
    TC_FENCE_AFTER();

    // --- epilogue: Y = D2 / ssum, written directly as bf16 hi/lo ---
    if (wid < 4) {
        uint32_t r0[32], r1[32];
        tc_ld32(r0, tmem + D2T);
        tc_ld32(r1, tmem + D2T + 32);
        TC_WAIT_LD();
        int m = wid * 32 + lane, h = m >> 4, tqq = m & 15;
        float inv = 1.f / ssum;
        size_t yb = (size_t)(n * TT + t0 + tqq) * HD + h * 64;
        #pragma unroll
        for (int j = 0; j < 16; j++) {
            float v0 = __uint_as_float(r0[2*j])   * inv;
            float v1 = __uint_as_float(r0[2*j+1]) * inv;
            __nv_bfloat16 h0, l0, h1, l1;
            split1(v0, h0, l0); split1(v1, h1, l1);
            *(uint32_t*)&g_Yh[yb + 2*j] = packhl(h0, h1);
            *(uint32_t*)&g_Yl[yb + 2*j] = packhl(l0, l1);
        }
        #pragma unroll
        for (int j = 0; j < 16; j++) {
            float v0 = __uint_as_float(r1[2*j])   * inv;
            float v1 = __uint_as_float(r1[2*j+1]) * inv;
            __nv_bfloat16 h0, l0, h1, l1;
            split1(v0, h0, l0); split1(v1, h1, l1);
            *(uint32_t*)&g_Yh[yb + 32 + 2*j] = packhl(h0, h1);
            *(uint32_t*)&g_Yl[yb + 32 + 2*j] = packhl(l0, l1);
        }
        TC_FENCE_BEFORE();
    }
    __syncthreads();
    if (wid == 0) TC_DEALLOC(tmem, 256);
#endif // TC_OK
}

// ---------------- fallback FFMA GEMMs + SIMT attention (plain pass) --------
__global__ __launch_bounds__(256) void sgemm128_tn(
    const float* __restrict__ X,
    const float* __restrict__ wK, const float* __restrict__ wV,
    const float* __restrict__ wQ)
{
#if !TC_OK
    const float* B; float* C;
    if      (blockIdx.z == 0) { B = wK; C = g_K; }
    else if (blockIdx.z == 1) { B = wV; C = g_V; }
    else                      { B = wQ; C = g_Q; }

    __shared__ float As[8][128];
    __shared__ float Bs[8][128];
    const int tid  = threadIdx.x;
    const int row0 = blockIdx.y * 128;
    const int col0 = blockIdx.x * 128;
    const int lr = tid >> 1, lc = (tid & 1) * 4;
    const int ty = tid >> 4, tx = tid & 15;

    float acc[8][8];
    #pragma unroll
    for (int i = 0; i < 8; i++)
        #pragma unroll
        for (int j = 0; j < 8; j++) acc[i][j] = 0.f;

    const float* Ap = X + (row0 + lr) * DMD + lc;
    const float* Bp = B + (col0 + lr) * DMD + lc;

    for (int k0 = 0; k0 < DMD; k0 += 8) {
        float4 av = *(const float4*)(Ap + k0);
        float4 bv = *(const float4*)(Bp + k0);
        As[lc+0][lr] = av.x; As[lc+1][lr] = av.y; As[lc+2][lr] = av.z; As[lc+3][lr] = av.w;
        Bs[lc+0][lr] = bv.x; Bs[lc+1][lr] = bv.y; Bs[lc+2][lr] = bv.z; Bs[lc+3][lr] = bv.w;
        __syncthreads();
        #pragma unroll
        for (int kk = 0; kk < 8; kk++) {
            float a[8], b[8];
            *(float4*)&a[0] = *(const float4*)&As[kk][ty*8];
            *(float4*)&a[4] = *(const float4*)&As[kk][ty*8+4];
            *(float4*)&b[0] = *(const float4*)&Bs[kk][tx*8];
            *(float4*)&b[4] = *(const float4*)&Bs[kk][tx*8+4];
            #pragma unroll
            for (int i = 0; i < 8; i++)
                #pragma unroll
                for (int j = 0; j < 8; j++)
                    acc[i][j] = fmaf(a[i], b[j], acc[i][j]);
        }
        __syncthreads();
    }

    float* Cp = C + (row0 + ty*8) * HD + col0 + tx*8;
    #pragma unroll
    for (int i = 0; i < 8; i++) {
        *(float4*)(Cp + i*HD)     = make_float4(acc[i][0], acc[i][1], acc[i][2], acc[i][3]);
        *(float4*)(Cp + i*HD + 4) = make_float4(acc[i][4], acc[i][5], acc[i][6], acc[i][7]);
    }
#endif
}

__global__ __launch_bounds__(256) void sgemm128_nn(
    const float* __restrict__ B, float* __restrict__ C)
{
#if !TC_OK
    __shared__ float As[8][128];
    __shared__ float Bs[8][128];
    const int tid  = threadIdx.x;
    const int row0 = blockIdx.y * 128;
    const int col0 = blockIdx.x * 128;
    const int alr = tid >> 1, alc = (tid & 1) * 4;
    const int blr = tid >> 5, blc = (tid & 31) * 4;
    const int ty = tid >> 4, tx = tid & 15;

    float acc[8][8];
    #pragma unroll
    for (int i = 0; i < 8; i++)
        #pragma unroll
        for (int j = 0; j < 8; j++) acc[i][j] = 0.f;

    for (int k0 = 0; k0 < HD; k0 += 8) {
        float4 av = *(const float4*)&g_Y[(row0 + alr)*HD + k0 + alc];
        As[alc+0][alr] = av.x; As[alc+1][alr] = av.y; As[alc+2][alr] = av.z; As[alc+3][alr] = av.w;
        float4 bv = *(const float4*)&B[(k0 + blr)*DMD + col0 + blc];
        *(float4*)&Bs[blr][blc] = bv;
        __syncthreads();
        #pragma unroll
        for (int kk = 0; kk < 8; kk++) {
            float a[8], b[8];
            *(float4*)&a[0] = *(const float4*)&As[kk][ty*8];
            *(float4*)&a[4] = *(const float4*)&As[kk][ty*8+4];
            *(float4*)&b[0] = *(const float4*)&Bs[kk][tx*8];
            *(float4*)&b[4] = *(const float4*)&Bs[kk][tx*8+4];
            #pragma unroll
            for (int i = 0; i < 8; i++)
                #pragma unroll
                for (int j = 0; j < 8; j++)
                    acc[i][j] = fmaf(a[i], b[j], acc[i][j]);
        }
        __syncthreads();
    }

    float* Cp = C + (row0 + ty*8)*DMD + col0 + tx*8;
    #pragma unroll
    for (int i = 0; i < 8; i++) {
        *(float4*)(Cp + i*DMD)     = make_float4(acc[i][0], acc[i][1], acc[i][2], acc[i][3]);
        *(float4*)(Cp + i*DMD + 4) = make_float4(acc[i][4], acc[i][5], acc[i][6], acc[i][7]);
    }
#endif
}

#define TS 16
#define SSPAN 47
#define SROW 65
#define ATTN_SMEM ((2*EE*SSPAN*SROW + 8*64 + 8*128) * 4)

__global__ __launch_bounds__(256) void attn_simt(
    const float* __restrict__ iK, const float* __restrict__ iV)
{
#if !TC_OK
    extern __shared__ float fsm[];
    float* sK = fsm;
    float* sV = sK + EE*SSPAN*SROW;
    float* sQ = sV + EE*SSPAN*SROW;
    float* sA = sQ + 8*64;

    const int n  = blockIdx.y;
    const int t0 = blockIdx.x * TS;
    const int tid = threadIdx.x;

    for (int idx = tid; idx < EE*SSPAN*DD; idx += 256) {
        int d = idx & 63;
        int r = (idx >> 6) % SSPAN;
        int e = idx / (SSPAN*DD);
        int s = t0 - 31 + r;
        float kv, vv;
        if (s >= 0) {
            size_t g = ((size_t)(n*EE + e)*TT + s)*DD + d;
            kv = __bfloat162float(g_sKh[g]) + __bfloat162float(g_sKl[g]);
            vv = __bfloat162float(g_sVh[g]) + __bfloat162float(g_sVl[g]);
        } else {
            int g = (e*LL + (s + 32))*DD + d;
            kv = iK[g]; vv = iV[g];
        }
        sK[(e*SSPAN + r)*SROW + d] = kv;
        sV[(e*SSPAN + r)*SROW + d] = vv;
    }
    __syncthreads();

    const int w = tid >> 5, lane = tid & 31;
    for (int task = w; task < TS*HH; task += 8) {
        int tq = task & (TS - 1);
        int h  = task >> 4;
        int nt = n*TT + t0 + tq;

        sQ[w*64 + lane]      = g_Q[nt*HD + h*64 + lane]      * 0.125f;
        sQ[w*64 + lane + 32] = g_Q[nt*HD + h*64 + lane + 32] * 0.125f;
        __syncwarp();

        float sc[4] = {0.f,0.f,0.f,0.f};
        #pragma unroll 4
        for (int d = 0; d < 64; d++) {
            float q = sQ[w*64 + d];
            #pragma unroll
            for (int e = 0; e < EE; e++)
                sc[e] = fmaf(q, sK[(e*SSPAN + tq + lane)*SROW + d], sc[e]);
        }
        float mx = fmaxf(fmaxf(sc[0], sc[1]), fmaxf(sc[2], sc[3]));
        #pragma unroll
        for (int o = 16; o; o >>= 1) mx = fmaxf(mx, __shfl_xor_sync(0xffffffffu, mx, o));
        float ssum = 0.f;
        #pragma unroll
        for (int e = 0; e < EE; e++) { sc[e] = __expf(sc[e] - mx); ssum += sc[e]; }
        #pragma unroll
        for (int o = 16; o; o >>= 1) ssum += __shfl_xor_sync(0xffffffffu, ssum, o);
        float inv = 1.f / ssum;
        #pragma unroll
        for (int e = 0; e < EE; e++) sA[w*128 + e*32 + lane] = sc[e] * inv;
        __syncwarp();

        float o0 = 0.f, o1 = 0.f;
        #pragma unroll 2
        for (int e = 0; e < EE; e++)
            for (int j = 0; j < LL; j++) {
                float a = sA[w*128 + e*32 + j];
                int base = (e*SSPAN + tq + j)*SROW;
                o0 = fmaf(a, sV[base + lane],      o0);
                o1 = fmaf(a, sV[base + lane + 32], o1);
            }
        g_Y[nt*HD + h*64 + lane]      = o0;
        g_Y[nt*HD + h*64 + lane + 32] = o1;
        __syncwarp();
    }
#endif
}

// ---------------- G projection fallback (plain pass only): raw scores ------
__global__ __launch_bounds__(256) void gproj_fb(
    const float* __restrict__ X, const float* __restrict__ wG)
{
#if !TC_OK
    __shared__ float As[32][32];
    __shared__ float Bs[32][33];
    const int tid  = threadIdx.x;
    const int row0 = blockIdx.x * 32;
    const int tx = tid & 31, ty = tid >> 5;
    const int lr = tid >> 3, lc = (tid & 7) * 4;

    float acc[4] = {0.f, 0.f, 0.f, 0.f};
    for (int k0 = 0; k0 < DMD; k0 += 32) {
        float4 xv = *(const float4*)&X[(row0 + lr) * DMD + k0 + lc];
        *(float4*)&As[lr][lc] = xv;
        float4 wv = *(const float4*)&wG[lr * DMD + k0 + lc];
        Bs[lr][lc] = wv.x; Bs[lr][lc+1] = wv.y; Bs[lr][lc+2] = wv.z; Bs[lr][lc+3] = wv.w;
        __syncthreads();
        #pragma unroll
        for (int kk = 0; kk < 32; kk++) {
            float b = Bs[tx][kk];
            #pragma unroll
            for (int i = 0; i < 4; i++)
                acc[i] = fmaf(As[ty*4+i][kk], b, acc[i]);
        }
        __syncthreads();
    }
    #pragma unroll
    for (int i = 0; i < 4; i++)
        g_Gpre[(size_t)(row0 + ty*4 + i) * HD + tx] = acc[i];
#endif
}

// ---------------- gating mix + A (cooperative sigmoid) ---------------------
__global__ __launch_bounds__(256) void gate_kernel(const float* __restrict__ bG)
{
    __shared__ float sg[4][32];           // sigmoid gate values per token
    const int tid = threadIdx.x;
    const int nt0 = blockIdx.x * 4;

    if (tid < 128) {                      // one sigmoid per thread
        int tok = tid >> 5, j = tid & 31;
        float raw = g_Gpre[(size_t)(nt0 + tok) * HD + j] + bG[j];
        sg[tok][j] = 1.f / (1.f + __expf(-raw));
    }
    __syncthreads();

    if (tid < 16) {                       // A = 1 - sum_h g
        int tok = tid >> 2, e = tid & 3;
        float s = 0.f;
        #pragma unroll
        for (int h = 0; h < HH; h++) s += sg[tok][h*4 + e];
        int nt = nt0 + tok;
        int n = nt >> 11, t = nt & (TT - 1);
        g_A[(n*EE + e)*TT + t] = 1.f - s;
    }

    const int tok = tid >> 6;
    const int nt  = nt0 + tok;
    const int d   = tid & 63;
    const int n   = nt >> 11;
    const int t   = nt & (TT - 1);

    float sKv[4] = {0.f,0.f,0.f,0.f}, sVv[4] = {0.f,0.f,0.f,0.f};
    #pragma unroll
    for (int h = 0; h < HH; h++) {
        float kv = g_K[nt*HD + h*64 + d];
        float vv = g_V[nt*HD + h*64 + d];
        #pragma unroll
        for (int e = 0; e < EE; e++) {
            float g = sg[tok][h*4 + e];   // LDS broadcast within warp
            sKv[e] = fmaf(g, kv, sKv[e]);
            sVv[e] = fmaf(g, vv, sVv[e]);
        }
    }
    #pragma unroll
    for (int e = 0; e < EE; e++) {
        int o = ((n*EE + e)*TT + t) * DD + d;
        g_gK[o] = sKv[e];
        g_gV[o] = sVv[e];
    }
}

// ---------------- stride-32 recurrence (pipelined loads) -------------------
__global__ __launch_bounds__(256) void scan_kernel(
    const float* __restrict__ iK, const float* __restrict__ iV)
{
    const int idx = blockIdx.x * 256 + threadIdx.x;   // 32768 threads
    const int d = idx & 63;
    const int p = (idx >> 6) & 31;
    const int e = (idx >> 11) & 3;
    const int n = (idx >> 13) & 1;
    const int kv = idx >> 14;

    const float* init = kv ? iV : iK;
    const float* gsrc = kv ? g_gV : g_gK;
    __nv_bfloat16* dh = kv ? g_sVh : g_sKh;
    __nv_bfloat16* dl = kv ? g_sVl : g_sKl;

    float pk = init[(e*LL + p)*DD + d];
    const int rowbase = (n*EE + e) * TT;

    float aA[8], gA[8], aB[8], gB[8], aC[8], gC[8];
#define LOADG(av, gv, grp)                                          \
    _Pragma("unroll")                                               \
    for (int i = 0; i < 8; i++) {                                   \
        int t = ((grp)*8 + i)*LL + p;                               \
        av[i] = __ldg(&g_A[rowbase + t]);                           \
        gv[i] = __ldg(&gsrc[(rowbase + t)*DD + d]);                 \
    }
    LOADG(aA, gA, 0);
    LOADG(aB, gB, 1);
    #pragma unroll
    for (int m = 0; m < 8; m++) {        // 8 groups of 8 steps
        if (m + 2 < 8) { LOADG(aC, gC, m + 2); }
        #pragma unroll
        for (int i = 0; i < 8; i++) {
            pk = fmaf(aA[i], pk, gA[i]);
            __nv_bfloat16 h, l;
            split1(pk, h, l);
            int o = (rowbase + (m*8 + i)*LL + p)*DD + d;
            dh[o] = h; dl[o] = l;
        }
        #pragma unroll
        for (int i = 0; i < 8; i++) { aA[i] = aB[i]; gA[i] = gB[i];
                                      aB[i] = aC[i]; gB[i] = gC[i]; }
    }
#undef LOADG
}

// ---------------- launcher -------------------------------------------------
extern "C" void kernel_launch(void* const* d_in, const int* in_sizes, int n_in,
                              void* d_out, int out_size)
{
    const float* X  = (const float*)d_in[0];
    const float* wG = (const float*)d_in[1];
    const float* bG = (const float*)d_in[2];
    const float* wK = (const float*)d_in[3];
    const float* wV = (const float*)d_in[4];
    const float* wQ = (const float*)d_in[5];
    const float* wO = (const float*)d_in[6];
    const float* iK = (const float*)d_in[7];
    const float* iV = (const float*)d_in[8];
    float* out = (float*)d_out;
    (void)in_sizes; (void)n_in; (void)out_size;

    void *pXh, *pXl, *pWh, *pWl, *pWOh, *pWOl, *pYh, *pYl, *pK, *pV, *pQ, *pGp;
    cudaGetSymbolAddress(&pXh, g_Xh);   cudaGetSymbolAddress(&pXl, g_Xl);
    cudaGetSymbolAddress(&pWh, g_Wh);   cudaGetSymbolAddress(&pWl, g_Wl);
    cudaGetSymbolAddress(&pWOh, g_WOh); cudaGetSymbolAddress(&pWOl, g_WOl);
    cudaGetSymbolAddress(&pYh, g_Yh);   cudaGetSymbolAddress(&pYl, g_Yl);
    cudaGetSymbolAddress(&pK, g_K); cudaGetSymbolAddress(&pV, g_V);
    cudaGetSymbolAddress(&pQ, g_Q); cudaGetSymbolAddress(&pGp, g_Gpre);

    // On sm_10x the tcgen05 cubin is loaded; fallback launches are dead weight.
    int dev = 0, ccmaj = 0;
    cudaGetDevice(&dev);
    cudaDeviceGetAttribute(&ccmaj, cudaDevAttrComputeCapabilityMajor, dev);
    const bool tc = (ccmaj == 10);

    cudaFuncSetAttribute(attn_simt,
                         cudaFuncAttributeMaxDynamicSharedMemorySize, ATTN_SMEM);
    cudaFuncSetAttribute(attn_tc,
                         cudaFuncAttributeMaxDynamicSharedMemorySize, ATC_SMEM);
    cudaFuncSetAttribute(tc_gemm,
                         cudaFuncAttributeMaxDynamicSharedMemorySize, TC_SMEM);

    // split X + wK/wV/wQ + wG (+ zero pad) + wO transpose in ONE launch
    split_all<<<6272, 256>>>(X, wK, wV, wQ, wG, wO);

    // K/V/Q/G projections fused: 13 col tiles (12 proj + 1 G), occ-3, one wave
    tc_gemm<<<dim3(13, 32), 256, TC_SMEM>>>(
        (const __nv_bfloat16*)pXh, (const __nv_bfloat16*)pXl,
        (const __nv_bfloat16*)pWh, (const __nv_bfloat16*)pWl,
        DMD, (float*)pK, (float*)pV, (float*)pQ, (float*)pGp, HD);
    if (!tc) {
        sgemm128_tn<<<dim3(4, 32, 3), 256>>>(X, wK, wV, wQ);
        gproj_fb<<<128, 256>>>(X, wG);
    }

    gate_kernel<<<NT/4, 256>>>(bG);
    scan_kernel<<<128, 256>>>(iK, iV);

    attn_tc<<<dim3(TT/16, NB), 256, ATC_SMEM>>>(iK, iV);
    if (!tc)
        attn_simt<<<dim3(TT/TS, NB), 256, ATTN_SMEM>>>(iK, iV);

    // output projection out = Y @ wO (attn_tc wrote Yh/Yl directly)
    tc_gemm<<<dim3(8, 32), 256, TC_SMEM>>>(
        (const __nv_bfloat16*)pYh, (const __nv_bfloat16*)pYl,
        (const __nv_bfloat16*)pWOh, (const __nv_bfloat16*)pWOl,
        HD, out, out, out, out, DMD);
    if (!tc)
        sgemm128_nn<<<dim3(8, 32), 256>>>(wO, out);
}

// round 17
// speedup vs baseline: 1.1824x; 1.0392x over previous
#include <cuda_runtime.h>
#include <cuda_bf16.h>
#include <cstdint>

// Arch gate: tcgen05 only exists in the sm_103a/sm_100a-specific passes.
#if !defined(__CUDA_ARCH__) || defined(__CUDA_ARCH_FEAT_SM103_ALL) || defined(__CUDA_ARCH_FEAT_SM100_ALL)
#define TC_OK 1
#else
#define TC_OK 0
#endif

// Problem constants
#define NB 2
#define TT 2048
#define DMD 1024
#define HH 8
#define EE 4
#define LL 32
#define DD 64
#define NT (NB*TT)      // 4096
#define HD (HH*DD)      // 512

// ---------------- scratch (device globals; no allocation allowed) ----------
__device__ float g_K[NT*HD];
__device__ float g_V[NT*HD];
__device__ float g_Q[NT*HD];
__device__ float g_Gpre[NT*HD];     // raw G scores in cols [0,32) of each 512-row
__device__ float g_A[NB*EE*TT];
__device__ float g_gK[NB*EE*TT*DD];
__device__ float g_gV[NB*EE*TT*DD];
__device__ float g_Y[NT*HD];

// scan outputs as bf16 hi/lo (consumed by tensor attention)
__device__ __nv_bfloat16 g_sKh[NB*EE*TT*DD], g_sKl[NB*EE*TT*DD];
__device__ __nv_bfloat16 g_sVh[NB*EE*TT*DD], g_sVl[NB*EE*TT*DD];

// bf16 split operands for tensor-core GEMMs
// W layout: [wK 512 | wV 512 | wQ 512 | wG 32 + zero-pad 96] rows of 1024
__device__ __nv_bfloat16 g_Xh[NT*DMD], g_Xl[NT*DMD];
__device__ __nv_bfloat16 g_Wh[(3*HD + 128)*DMD], g_Wl[(3*HD + 128)*DMD];
__device__ __nv_bfloat16 g_WOh[DMD*HD], g_WOl[DMD*HD];
__device__ __nv_bfloat16 g_Yh[NT*HD], g_Yl[NT*HD];

// ---------------- PTX helpers ----------------------------------------------
__device__ __forceinline__ uint32_t smem_u32(const void* p) {
    uint32_t a;
    asm("{ .reg .u64 t; cvta.to.shared.u64 t, %1; cvt.u32.u64 %0, t; }"
        : "=r"(a) : "l"(p));
    return a;
}
__device__ __forceinline__ uint32_t elect_one() {
    uint32_t pred;
    asm volatile("{ .reg .pred p; elect.sync _|p, 0xFFFFFFFF; selp.b32 %0, 1, 0, p; }"
                 : "=r"(pred));
    return pred;
}
#define MB_INIT(mb, cnt) \
    asm volatile("mbarrier.init.shared.b64 [%0], %1;" :: "r"(mb), "r"(cnt) : "memory")
#define FENCE_ASYNC()     asm volatile("fence.proxy.async.shared::cta;" ::: "memory")
#define CPA16(dst, src) \
    asm volatile("cp.async.cg.shared.global [%0], [%1], 16;" :: "r"(dst), "l"(src) : "memory")
#define CPA_COMMIT() asm volatile("cp.async.commit_group;" ::: "memory")
#define CPA_WAIT0()  asm volatile("cp.async.wait_group 0;" ::: "memory")

__device__ __forceinline__ void mb_wait(uint32_t mb, uint32_t parity) {
    uint32_t done;
    asm volatile("{ .reg .pred p; mbarrier.try_wait.parity.acquire.cta.shared::cta.b64 p, [%1], %2;"
                 " selp.b32 %0, 1, 0, p; }" : "=r"(done) : "r"(mb), "r"(parity) : "memory");
    if (!done) {
        asm volatile("{ .reg .pred P1; WL%=:"
                     " mbarrier.try_wait.parity.acquire.cta.shared::cta.b64 P1, [%0], %1, 0x989680;"
                     " @P1 bra.uni WD%=; bra.uni WL%=; WD%=: }"
                     :: "r"(mb), "r"(parity) : "memory");
    }
}

#if TC_OK
#define TC_ALLOC(sm, n) \
    asm volatile("tcgen05.alloc.cta_group::1.sync.aligned.shared::cta.b32 [%0], %1;" \
                 :: "r"(sm), "r"(n) : "memory")
#define TC_DEALLOC(tm, n) \
    asm volatile("tcgen05.dealloc.cta_group::1.sync.aligned.b32 %0, %1;" :: "r"(tm), "r"(n))
#define TC_RELINQ() \
    asm volatile("tcgen05.relinquish_alloc_permit.cta_group::1.sync.aligned;")
#define TC_COMMIT(mb) \
    asm volatile("tcgen05.commit.cta_group::1.mbarrier::arrive::one.shared::cluster.b64 [%0];" \
                 :: "r"(mb) : "memory")
#define TC_FENCE_AFTER()  asm volatile("tcgen05.fence::after_thread_sync;" ::: "memory")
#define TC_FENCE_BEFORE() asm volatile("tcgen05.fence::before_thread_sync;" ::: "memory")
#define TC_WAIT_LD()      asm volatile("tcgen05.wait::ld.sync.aligned;" ::: "memory")

__device__ __forceinline__ void mma_f16_ss(uint32_t d, uint64_t ad, uint64_t bd,
                                           uint32_t idesc, uint32_t en) {
    asm volatile("{ .reg .pred p; setp.ne.u32 p, %5, 0;"
                 " tcgen05.mma.cta_group::1.kind::f16 [%0], %1, %2, %3, {%4,%4,%4,%4}, p; }"
                 :: "r"(d), "l"(ad), "l"(bd), "r"(idesc), "r"(0u), "r"(en) : "memory");
}
__device__ __forceinline__ void tc_ld32(uint32_t* r, uint32_t addr) {
    asm volatile("tcgen05.ld.sync.aligned.32x32b.x32.b32 "
        "{%0,%1,%2,%3,%4,%5,%6,%7,%8,%9,%10,%11,%12,%13,%14,%15,"
        "%16,%17,%18,%19,%20,%21,%22,%23,%24,%25,%26,%27,%28,%29,%30,%31}, [%32];"
        : "=r"(r[0]),"=r"(r[1]),"=r"(r[2]),"=r"(r[3]),"=r"(r[4]),"=r"(r[5]),"=r"(r[6]),"=r"(r[7]),
          "=r"(r[8]),"=r"(r[9]),"=r"(r[10]),"=r"(r[11]),"=r"(r[12]),"=r"(r[13]),"=r"(r[14]),"=r"(r[15]),
          "=r"(r[16]),"=r"(r[17]),"=r"(r[18]),"=r"(r[19]),"=r"(r[20]),"=r"(r[21]),"=r"(r[22]),"=r"(r[23]),
          "=r"(r[24]),"=r"(r[25]),"=r"(r[26]),"=r"(r[27]),"=r"(r[28]),"=r"(r[29]),"=r"(r[30]),"=r"(r[31])
        : "r"(addr));
}
#endif // TC_OK

static constexpr uint64_t DESC_BASE_SW128 =
    (uint64_t(2) << 61) | (uint64_t(1) << 46) | (uint64_t(64) << 32) | (uint64_t(1) << 16);
#define MK_DESC(a) (DESC_BASE_SW128 | ((uint64_t)((a) >> 4) & 0x3FFF))
#define SWZ(o) ((o) ^ (((o) >> 3) & 0x70))

// idesc: F32 accum, BF16 a/b, M=128; N field = (N/8)<<17
#define ID_N128 0x8200490u
#define ID_N192 0x8300490u
#define ID_N64  0x8100490u

__device__ __forceinline__ void split1(float x, __nv_bfloat16& h, __nv_bfloat16& l) {
    h = __float2bfloat16(x);
    l = __float2bfloat16(x - __bfloat162float(h));
}
__device__ __forceinline__ uint32_t packhl(__nv_bfloat16 a, __nv_bfloat16 b) {
    __nv_bfloat162 t(a, b);
    return *(uint32_t*)&t;
}

// ---------------- split kernels --------------------------------------------
// One launch splits X, wK/wV/wQ, wG, zero-pads the wG tile, and
// transpose-splits wO.
__global__ __launch_bounds__(256) void split_all(
    const float* __restrict__ X,
    const float* __restrict__ wK, const float* __restrict__ wV,
    const float* __restrict__ wQ, const float* __restrict__ wG,
    const float* __restrict__ wO)
{
    __shared__ float t[32][33];
    int b = blockIdx.x;
    if (b >= 5760) {                      // wO transpose-split
        int j = b - 5760;
        int n0 = (j & 31) * 32, k0 = (j >> 5) * 32;
        int tx = threadIdx.x & 31, ty = threadIdx.x >> 5;
        #pragma unroll
        for (int jj = 0; jj < 32; jj += 8)
            t[ty + jj][tx] = wO[(k0 + ty + jj) * DMD + n0 + tx];
        __syncthreads();
        #pragma unroll
        for (int jj = 0; jj < 32; jj += 8) {
            __nv_bfloat16 h, l;
            split1(t[tx][ty + jj], h, l);
            g_WOh[(n0 + ty + jj) * HD + k0 + tx] = h;
            g_WOl[(n0 + ty + jj) * HD + k0 + tx] = l;
        }
        return;
    }
    if (b >= 5664) {                      // zero-pad
        int i = ((b - 5664) * 256 + threadIdx.x) * 4;
        size_t o = (size_t)(3*HD + 32) * DMD + i;
        *(uint64_t*)(g_Wh + o) = 0ull;
        *(uint64_t*)(g_Wl + o) = 0ull;
        return;
    }
    const float* s;
    __nv_bfloat16 *h, *l;
    int i;
    if (b < 4096) {
        s = X; h = g_Xh; l = g_Xl;
        i = b * 256 + threadIdx.x;
    } else if (b < 5632) {
        int j = b - 4096;
        int mat = j >> 9;
        s = (mat == 0) ? wK : (mat == 1) ? wV : wQ;
        h = g_Wh + (size_t)mat * HD * DMD;
        l = g_Wl + (size_t)mat * HD * DMD;
        i = (j & 511) * 256 + threadIdx.x;
    } else {                              // wG: 32 rows x 1024 = 8192 float4
        s = wG;
        h = g_Wh + (size_t)3 * HD * DMD;
        l = g_Wl + (size_t)3 * HD * DMD;
        i = (b - 5632) * 256 + threadIdx.x;
    }
    i <<= 2;
    float4 v = *(const float4*)(s + i);
    float xs[4] = {v.x, v.y, v.z, v.w};
    __nv_bfloat16 hh[4], ll[4];
    #pragma unroll
    for (int j = 0; j < 4; j++) split1(xs[j], hh[j], ll[j]);
    ((__nv_bfloat162*)(h + i))[0] = __nv_bfloat162(hh[0], hh[1]);
    ((__nv_bfloat162*)(h + i))[1] = __nv_bfloat162(hh[2], hh[3]);
    ((__nv_bfloat162*)(l + i))[0] = __nv_bfloat162(ll[0], ll[1]);
    ((__nv_bfloat162*)(l + i))[1] = __nv_bfloat162(ll[2], ll[3]);
}

// ---------------- tcgen05 GEMM (sm_103a pass only) -------------------------
// PROVEN BEST: 128x128 tiles, single 64KB stage, occ-3; 8 warps for fast
// cp.async issue. MMA from warp 0, epilogue warps 0-3. Fused 13-col launch.
#define TC_SMEM (1024 + 65536)

__global__ __launch_bounds__(256, 3) void tc_gemm(
    const __nv_bfloat16* __restrict__ Ah, const __nv_bfloat16* __restrict__ Al,
    const __nv_bfloat16* __restrict__ Bh, const __nv_bfloat16* __restrict__ Bl,
    int K, float* C0, float* C1, float* C2, float* C3, int colmat)
{
#if TC_OK
    extern __shared__ char smem[];
    uint32_t sb = smem_u32(smem);
    const int tid = threadIdx.x, wid = tid >> 5, lid = tid & 31;
    const int row0 = blockIdx.y * 128, col0 = blockIdx.x * 128;

    if (wid == 0) { TC_ALLOC(sb, 128); TC_RELINQ(); }
    __syncthreads();
    uint32_t tmem;
    asm volatile("ld.shared.b32 %0, [%1];" : "=r"(tmem) : "r"(sb));
    if (tid == 0) MB_INIT(sb + 8, 1);
    __syncthreads();

    const __nv_bfloat16* src[4] = { Ah + (size_t)row0 * K, Al + (size_t)row0 * K,
                                    Bh + (size_t)col0 * K, Bl + (size_t)col0 * K };
    const int NC = K >> 6;
    uint32_t stb = sb + 1024;
    uint64_t dA[2] = { MK_DESC(stb), MK_DESC(stb + 16384) };
    uint64_t dB[2] = { MK_DESC(stb + 32768), MK_DESC(stb + 49152) };

    int ph = 0;
    for (int c = 0; c < NC; c++) {
        if (c > 0) { mb_wait(sb + 8, ph); ph ^= 1; }
        int kof = c * 64;
        #pragma unroll
        for (int u = tid; u < 4096; u += 256) {
            int buf = u >> 10, wi = u & 1023;
            int r = wi >> 3, cb = wi & 7;
            uint32_t off = SWZ((uint32_t)(r * 128 + cb * 16));
            CPA16(stb + buf * 16384 + off, src[buf] + (size_t)r * K + kof + cb * 8);
        }
        CPA_COMMIT();
        CPA_WAIT0();
        FENCE_ASYNC();
        __syncthreads();
        if (wid == 0 && elect_one()) {
            #pragma unroll
            for (int ks = 0; ks < 4; ks++)
                mma_f16_ss(tmem, dA[0] + ks * 2, dB[0] + ks * 2, ID_N128, !(c == 0 && ks == 0));
            #pragma unroll
            for (int ks = 0; ks < 4; ks++)
                mma_f16_ss(tmem, dA[0] + ks * 2, dB[1] + ks * 2, ID_N128, 1);
            #pragma unroll
            for (int ks = 0; ks < 4; ks++)
                mma_f16_ss(tmem, dA[1] + ks * 2, dB[0] + ks * 2, ID_N128, 1);
            TC_COMMIT(sb + 8);
        }
        __syncthreads();
    }
    mb_wait(sb + 8, ph);
    TC_FENCE_AFTER();

    if (wid < 4) {
        int mat = col0 / colmat;
        float* C = (mat == 0) ? C0 : (mat == 1) ? C1 : (mat == 2) ? C2 : C3;
        int lc0 = col0 - mat * colmat;
        float* dst = C + (size_t)(row0 + wid * 32 + lid) * colmat + lc0;
        #pragma unroll
        for (int pass = 0; pass < 4; pass++) {
            uint32_t r[32];
            tc_ld32(r, tmem + pass * 32);
            TC_WAIT_LD();
            #pragma unroll
            for (int j = 0; j < 8; j++)
                *(float4*)&dst[pass * 32 + j * 4] =
                    make_float4(__uint_as_float(r[j*4]),   __uint_as_float(r[j*4+1]),
                                __uint_as_float(r[j*4+2]), __uint_as_float(r[j*4+3]));
        }
        TC_FENCE_BEFORE();
    }
    __syncthreads();
    if (wid == 0) TC_DEALLOC(tmem, 128);
#endif // TC_OK
}

// ---------------- tensor-core windowed attention (sm_103a pass) ------------
#define D2T 192              // TMEM col offset of AV accumulator
#define AVH 1024
#define AVL (AVH + 24576)    // 25600
#define AQH 50176
#define AQL (AQH + 16384)    // 66560
#define AKH (AQL + 16384)    // 82944
#define AKL (AKH + 24576)    // 107520
#define APH 50176            // reuse Q/K region after MMA1
#define APL (APH + 49152)    // 99328
#define ATC_SMEM 148480

__global__ __launch_bounds__(256) void attn_tc(
    const float* __restrict__ iK, const float* __restrict__ iV)
{
#if TC_OK
    extern __shared__ char smem[];
    uint32_t sb = smem_u32(smem);
    const int tid = threadIdx.x, wid = tid >> 5, lane = tid & 31;
    const int n = blockIdx.y, t0 = blockIdx.x * 16;

    if (wid == 0) { TC_ALLOC(sb, 256); TC_RELINQ(); }
    __syncthreads();
    uint32_t tmem;
    asm volatile("ld.shared.b32 %0, [%1];" : "=r"(tmem) : "r"(sb));
    if (tid == 0) { MB_INIT(sb + 8, 1); MB_INIT(sb + 16, 1); }

    // --- stage Q (scaled by 1/8, hi/lo split), rows m = h*16+tq, SW128 ---
    for (int idx = tid; idx < 128 * 32; idx += 256) {
        int m = idx >> 5, d2 = (idx & 31) * 2;
        int h = m >> 4, tq = m & 15;
        const float* qp = &g_Q[(size_t)(n * TT + t0 + tq) * HD + h * 64 + d2];
        float x0 = qp[0] * 0.125f, x1 = qp[1] * 0.125f;
        __nv_bfloat16 h0, l0, h1, l1;
        split1(x0, h0, l0); split1(x1, h1, l1);
        uint32_t off = SWZ((uint32_t)(m * 128 + d2 * 2));
        *(uint32_t*)(smem + AQH + off) = packhl(h0, h1);
        *(uint32_t*)(smem + AQL + off) = packhl(l0, l1);
    }
    // --- stage K rows (key rr = e*48+r), 16B granules, SW128 K-major ---
    for (int idx = tid; idx < 192 * 8; idx += 256) {
        int rr = idx >> 3, gc = idx & 7;
        int e = rr / 48, r = rr - e * 48;
        int s = t0 - 31 + r;
        uint32_t off = SWZ((uint32_t)(rr * 128 + gc * 16));
        uint4 vh, vl;
        if (r == 47) {
            vh = make_uint4(0, 0, 0, 0); vl = vh;
        } else if (s >= 0) {
            size_t g = ((size_t)(n * EE + e) * TT + s) * 64 + gc * 8;
            vh = *(const uint4*)&g_sKh[g];
            vl = *(const uint4*)&g_sKl[g];
        } else {
            const float* ip = &iK[(size_t)(e * 32 + (s + 32)) * 64 + gc * 8];
            float4 f0 = *(const float4*)ip, f1 = *(const float4*)(ip + 4);
            float fx[8] = {f0.x, f0.y, f0.z, f0.w, f1.x, f1.y, f1.z, f1.w};
            uint32_t hw[4], lw[4];
            #pragma unroll
            for (int j = 0; j < 4; j++) {
                __nv_bfloat16 a, b, c2, d2b;
                split1(fx[2*j], a, b); split1(fx[2*j+1], c2, d2b);
                hw[j] = packhl(a, c2);
                lw[j] = packhl(b, d2b);
            }
            vh = make_uint4(hw[0], hw[1], hw[2], hw[3]);
            vl = make_uint4(lw[0], lw[1], lw[2], lw[3]);
        }
        *(uint4*)(smem + AKH + off) = vh;
        *(uint4*)(smem + AKL + off) = vl;
    }
    // --- stage V as B-operand blocked atoms: [64 dims] x [192 keys] ---
    for (int idx = tid; idx < 192 * 64; idx += 256) {
        int d = idx & 63, rr = idx >> 6;
        int e = rr / 48, r = rr - e * 48;
        int s = t0 - 31 + r;
        int atom = (d >> 3) + (rr >> 6) * 8;
        uint32_t off = SWZ((uint32_t)(atom * 1024 + (d & 7) * 128 + (rr & 63) * 2));
        __nv_bfloat16 vh, vl;
        if (r == 47) {
            vh = __float2bfloat16(0.f); vl = vh;
        } else if (s >= 0) {
            size_t g = ((size_t)(n * EE + e) * TT + s) * 64 + d;
            vh = g_sVh[g]; vl = g_sVl[g];
        } else {
            split1(iV[(size_t)(e * 32 + (s + 32)) * 64 + d], vh, vl);
        }
        *(__nv_bfloat16*)(smem + AVH + off) = vh;
        *(__nv_bfloat16*)(smem + AVL + off) = vl;
    }
    FENCE_ASYNC();
    __syncthreads();

    // --- MMA1: scores D1[128x192] = Q * K^T (3-term split) ---
    if (wid == 0 && elect_one()) {
        uint64_t dQh = MK_DESC(sb + AQH), dQl = MK_DESC(sb + AQL);
        uint64_t dKh = MK_DESC(sb + AKH), dKl = MK_DESC(sb + AKL);
        #pragma unroll
        for (int ks = 0; ks < 4; ks++)
            mma_f16_ss(tmem, dQh + ks * 2, dKh + ks * 2, ID_N192, ks != 0);
        #pragma unroll
        for (int ks = 0; ks < 4; ks++)
            mma_f16_ss(tmem, dQh + ks * 2, dKl + ks * 2, ID_N192, 1);
        #pragma unroll
        for (int ks = 0; ks < 4; ks++)
            mma_f16_ss(tmem, dQl + ks * 2, dKh + ks * 2, ID_N192, 1);
        TC_COMMIT(sb + 8);
    }
    mb_wait(sb + 8, 0);
    TC_FENCE_AFTER();

    // --- softmax: ONE LDTM sweep, scores register-resident; masked entries
    //     get a -1e30 sentinel so exp underflows to exactly 0 ---
    float ssum = 0.f;
    if (wid < 4) {
        const int m = wid * 32 + lane;
        const int tq = m & 15;
        float val[192];
        float mx = -1e30f;
        #pragma unroll
        for (int cc = 0; cc < 6; cc++) {
            uint32_t r32[32];
            tc_ld32(r32, tmem + cc * 32);
            TC_WAIT_LD();
            #pragma unroll
            for (int j = 0; j < 32; j++) {
                int c = cc * 32 + j;
                int r = c % 48;
                float sv = __uint_as_float(r32[j]);
                float v = (((unsigned)(r - tq)) < 32u) ? sv : -1e30f;
                val[c] = v;
                mx = fmaxf(mx, v);
            }
        }
        const int arow = m >> 3;
        const uint32_t ibase = (uint32_t)((m & 7) * 128);
        #pragma unroll
        for (int k = 0; k < 192; k += 2) {
            float ev0 = __expf(val[k]     - mx);   // sentinel -> underflow -> 0
            float ev1 = __expf(val[k + 1] - mx);
            ssum += ev0 + ev1;
            __nv_bfloat16 h0, l0, h1, l1;
            split1(ev0, h0, l0); split1(ev1, h1, l1);
            uint32_t off = SWZ((uint32_t)(((k >> 6) * 16 + arow) * 1024 + ibase + (k & 63) * 2));
            *(uint32_t*)(smem + APH + off) = packhl(h0, h1);
            *(uint32_t*)(smem + APL + off) = packhl(l0, l1);
        }
    }
    FENCE_ASYNC();
    __syncthreads();

    // --- MMA2: D2[128x64] = P * V (SS mode, 3-term split, K=192) ---
    if (wid == 0 && elect_one()) {
        uint64_t dPh = MK_DESC(sb + APH), dPl = MK_DESC(sb + APL);
        uint64_t dVh = MK_DESC(sb + AVH), dVl = MK_DESC(sb + AVL);
        #pragma unroll
        for (int ks = 0; ks < 12; ks++) {
            uint64_t ao = (uint64_t)((ks >> 2) * 1024 + (ks & 3) * 2);
            uint64_t bo = (uint64_t)((ks >> 2) * 512  + (ks & 3) * 2);
            mma_f16_ss(tmem + D2T, dPh + ao, dVh + bo, ID_N64, ks != 0);
        }
        #pragma unroll
        for (int ks = 0; ks < 12; ks++) {
            uint64_t ao = (uint64_t)((ks >> 2) * 1024 + (ks & 3) * 2);
            uint64_t bo = (uint64_t)((ks >> 2) * 512  + (ks & 3) * 2);
            mma_f16_ss(tmem + D2T, dPh + ao, dVl + bo, ID_N64, 1);
        }
        #pragma unroll
        for (int ks = 0; ks < 12; ks++) {
            uint64_t ao = (uint64_t)((ks >> 2) * 1024 + (ks & 3) * 2);
            uint64_t bo = (uint64_t)((ks >> 2) * 512  + (ks & 3) * 2);
            mma_f16_ss(tmem + D2T, dPl + ao, dVh + bo, ID_N64, 1);
        }
        TC_COMMIT(sb + 16);
    }
    mb_wait(sb + 16, 0);
    TC_FENCE_AFTER();

    // --- epilogue: Y = D2 / ssum, written directly as bf16 hi/lo ---
    if (wid < 4) {
        uint32_t r0[32], r1[32];
        tc_ld32(r0, tmem + D2T);
        tc_ld32(r1, tmem + D2T + 32);
        TC_WAIT_LD();
        int m = wid * 32 + lane, h = m >> 4, tqq = m & 15;
        float inv = 1.f / ssum;
        size_t yb = (size_t)(n * TT + t0 + tqq) * HD + h * 64;
        #pragma unroll
        for (int j = 0; j < 16; j++) {
            float v0 = __uint_as_float(r0[2*j])   * inv;
            float v1 = __uint_as_float(r0[2*j+1]) * inv;
            __nv_bfloat16 h0, l0, h1, l1;
            split1(v0, h0, l0); split1(v1, h1, l1);
            *(uint32_t*)&g_Yh[yb + 2*j] = packhl(h0, h1);
            *(uint32_t*)&g_Yl[yb + 2*j] = packhl(l0, l1);
        }
        #pragma unroll
        for (int j = 0; j < 16; j++) {
            float v0 = __uint_as_float(r1[2*j])   * inv;
            float v1 = __uint_as_float(r1[2*j+1]) * inv;
            __nv_bfloat16 h0, l0, h1, l1;
            split1(v0, h0, l0); split1(v1, h1, l1);
            *(uint32_t*)&g_Yh[yb + 32 + 2*j] = packhl(h0, h1);
            *(uint32_t*)&g_Yl[yb + 32 + 2*j] = packhl(l0, l1);
        }
        TC_FENCE_BEFORE();
    }
    __syncthreads();
    if (wid == 0) TC_DEALLOC(tmem, 256);
#endif // TC_OK
}

// ---------------- fallback FFMA GEMMs + SIMT attention (plain pass) --------
__global__ __launch_bounds__(256) void sgemm128_tn(
    const float* __restrict__ X,
    const float* __restrict__ wK, const float* __restrict__ wV,
    const float* __restrict__ wQ)
{
#if !TC_OK
    const float* B; float* C;
    if      (blockIdx.z == 0) { B = wK; C = g_K; }
    else if (blockIdx.z == 1) { B = wV; C = g_V; }
    else                      { B = wQ; C = g_Q; }

    __shared__ float As[8][128];
    __shared__ float Bs[8][128];
    const int tid  = threadIdx.x;
    const int row0 = blockIdx.y * 128;
    const int col0 = blockIdx.x * 128;
    const int lr = tid >> 1, lc = (tid & 1) * 4;
    const int ty = tid >> 4, tx = tid & 15;

    float acc[8][8];
    #pragma unroll
    for (int i = 0; i < 8; i++)
        #pragma unroll
        for (int j = 0; j < 8; j++) acc[i][j] = 0.f;

    const float* Ap = X + (row0 + lr) * DMD + lc;
    const float* Bp = B + (col0 + lr) * DMD + lc;

    for (int k0 = 0; k0 < DMD; k0 += 8) {
        float4 av = *(const float4*)(Ap + k0);
        float4 bv = *(const float4*)(Bp + k0);
        As[lc+0][lr] = av.x; As[lc+1][lr] = av.y; As[lc+2][lr] = av.z; As[lc+3][lr] = av.w;
        Bs[lc+0][lr] = bv.x; Bs[lc+1][lr] = bv.y; Bs[lc+2][lr] = bv.z; Bs[lc+3][lr] = bv.w;
        __syncthreads();
        #pragma unroll
        for (int kk = 0; kk < 8; kk++) {
            float a[8], b[8];
            *(float4*)&a[0] = *(const float4*)&As[kk][ty*8];
            *(float4*)&a[4] = *(const float4*)&As[kk][ty*8+4];
            *(float4*)&b[0] = *(const float4*)&Bs[kk][tx*8];
            *(float4*)&b[4] = *(const float4*)&Bs[kk][tx*8+4];
            #pragma unroll
            for (int i = 0; i < 8; i++)
                #pragma unroll
                for (int j = 0; j < 8; j++)
                    acc[i][j] = fmaf(a[i], b[j], acc[i][j]);
        }
        __syncthreads();
    }

    float* Cp = C + (row0 + ty*8) * HD + col0 + tx*8;
    #pragma unroll
    for (int i = 0; i < 8; i++) {
        *(float4*)(Cp + i*HD)     = make_float4(acc[i][0], acc[i][1], acc[i][2], acc[i][3]);
        *(float4*)(Cp + i*HD + 4) = make_float4(acc[i][4], acc[i][5], acc[i][6], acc[i][7]);
    }
#endif
}

__global__ __launch_bounds__(256) void sgemm128_nn(
    const float* __restrict__ B, float* __restrict__ C)
{
#if !TC_OK
    __shared__ float As[8][128];
    __shared__ float Bs[8][128];
    const int tid  = threadIdx.x;
    const int row0 = blockIdx.y * 128;
    const int col0 = blockIdx.x * 128;
    const int alr = tid >> 1, alc = (tid & 1) * 4;
    const int blr = tid >> 5, blc = (tid & 31) * 4;
    const int ty = tid >> 4, tx = tid & 15;

    float acc[8][8];
    #pragma unroll
    for (int i = 0; i < 8; i++)
        #pragma unroll
        for (int j = 0; j < 8; j++) acc[i][j] = 0.f;

    for (int k0 = 0; k0 < HD; k0 += 8) {
        float4 av = *(const float4*)&g_Y[(row0 + alr)*HD + k0 + alc];
        As[alc+0][alr] = av.x; As[alc+1][alr] = av.y; As[alc+2][alr] = av.z; As[alc+3][alr] = av.w;
        float4 bv = *(const float4*)&B[(k0 + blr)*DMD + col0 + blc];
        *(float4*)&Bs[blr][blc] = bv;
        __syncthreads();
        #pragma unroll
        for (int kk = 0; kk < 8; kk++) {
            float a[8], b[8];
            *(float4*)&a[0] = *(const float4*)&As[kk][ty*8];
            *(float4*)&a[4] = *(const float4*)&As[kk][ty*8+4];
            *(float4*)&b[0] = *(const float4*)&Bs[kk][tx*8];
            *(float4*)&b[4] = *(const float4*)&Bs[kk][tx*8+4];
            #pragma unroll
            for (int i = 0; i < 8; i++)
                #pragma unroll
                for (int j = 0; j < 8; j++)
                    acc[i][j] = fmaf(a[i], b[j], acc[i][j]);
        }
        __syncthreads();
    }

    float* Cp = C + (row0 + ty*8)*DMD + col0 + tx*8;
    #pragma unroll
    for (int i = 0; i < 8; i++) {
        *(float4*)(Cp + i*DMD)     = make_float4(acc[i][0], acc[i][1], acc[i][2], acc[i][3]);
        *(float4*)(Cp + i*DMD + 4) = make_float4(acc[i][4], acc[i][5], acc[i][6], acc[i][7]);
    }
#endif
}

#define TS 16
#define SSPAN 47
#define SROW 65
#define ATTN_SMEM ((2*EE*SSPAN*SROW + 8*64 + 8*128) * 4)

__global__ __launch_bounds__(256) void attn_simt(
    const float* __restrict__ iK, const float* __restrict__ iV)
{
#if !TC_OK
    extern __shared__ float fsm[];
    float* sK = fsm;
    float* sV = sK + EE*SSPAN*SROW;
    float* sQ = sV + EE*SSPAN*SROW;
    float* sA = sQ + 8*64;

    const int n  = blockIdx.y;
    const int t0 = blockIdx.x * TS;
    const int tid = threadIdx.x;

    for (int idx = tid; idx < EE*SSPAN*DD; idx += 256) {
        int d = idx & 63;
        int r = (idx >> 6) % SSPAN;
        int e = idx / (SSPAN*DD);
        int s = t0 - 31 + r;
        float kv, vv;
        if (s >= 0) {
            size_t g = ((size_t)(n*EE + e)*TT + s)*DD + d;
            kv = __bfloat162float(g_sKh[g]) + __bfloat162float(g_sKl[g]);
            vv = __bfloat162float(g_sVh[g]) + __bfloat162float(g_sVl[g]);
        } else {
            int g = (e*LL + (s + 32))*DD + d;
            kv = iK[g]; vv = iV[g];
        }
        sK[(e*SSPAN + r)*SROW + d] = kv;
        sV[(e*SSPAN + r)*SROW + d] = vv;
    }
    __syncthreads();

    const int w = tid >> 5, lane = tid & 31;
    for (int task = w; task < TS*HH; task += 8) {
        int tq = task & (TS - 1);
        int h  = task >> 4;
        int nt = n*TT + t0 + tq;

        sQ[w*64 + lane]      = g_Q[nt*HD + h*64 + lane]      * 0.125f;
        sQ[w*64 + lane + 32] = g_Q[nt*HD + h*64 + lane + 32] * 0.125f;
        __syncwarp();

        float sc[4] = {0.f,0.f,0.f,0.f};
        #pragma unroll 4
        for (int d = 0; d < 64; d++) {
            float q = sQ[w*64 + d];
            #pragma unroll
            for (int e = 0; e < EE; e++)
                sc[e] = fmaf(q, sK[(e*SSPAN + tq + lane)*SROW + d], sc[e]);
        }
        float mx = fmaxf(fmaxf(sc[0], sc[1]), fmaxf(sc[2], sc[3]));
        #pragma unroll
        for (int o = 16; o; o >>= 1) mx = fmaxf(mx, __shfl_xor_sync(0xffffffffu, mx, o));
        float ssum = 0.f;
        #pragma unroll
        for (int e = 0; e < EE; e++) { sc[e] = __expf(sc[e] - mx); ssum += sc[e]; }
        #pragma unroll
        for (int o = 16; o; o >>= 1) ssum += __shfl_xor_sync(0xffffffffu, ssum, o);
        float inv = 1.f / ssum;
        #pragma unroll
        for (int e = 0; e < EE; e++) sA[w*128 + e*32 + lane] = sc[e] * inv;
        __syncwarp();

        float o0 = 0.f, o1 = 0.f;
        #pragma unroll 2
        for (int e = 0; e < EE; e++)
            for (int j = 0; j < LL; j++) {
                float a = sA[w*128 + e*32 + j];
                int base = (e*SSPAN + tq + j)*SROW;
                o0 = fmaf(a, sV[base + lane],      o0);
                o1 = fmaf(a, sV[base + lane + 32], o1);
            }
        g_Y[nt*HD + h*64 + lane]      = o0;
        g_Y[nt*HD + h*64 + lane + 32] = o1;
        __syncwarp();
    }
#endif
}

// ---------------- G projection fallback (plain pass only): raw scores ------
__global__ __launch_bounds__(256) void gproj_fb(
    const float* __restrict__ X, const float* __restrict__ wG)
{
#if !TC_OK
    __shared__ float As[32][32];
    __shared__ float Bs[32][33];
    const int tid  = threadIdx.x;
    const int row0 = blockIdx.x * 32;
    const int tx = tid & 31, ty = tid >> 5;
    const int lr = tid >> 3, lc = (tid & 7) * 4;

    float acc[4] = {0.f, 0.f, 0.f, 0.f};
    for (int k0 = 0; k0 < DMD; k0 += 32) {
        float4 xv = *(const float4*)&X[(row0 + lr) * DMD + k0 + lc];
        *(float4*)&As[lr][lc] = xv;
        float4 wv = *(const float4*)&wG[lr * DMD + k0 + lc];
        Bs[lr][lc] = wv.x; Bs[lr][lc+1] = wv.y; Bs[lr][lc+2] = wv.z; Bs[lr][lc+3] = wv.w;
        __syncthreads();
        #pragma unroll
        for (int kk = 0; kk < 32; kk++) {
            float b = Bs[tx][kk];
            #pragma unroll
            for (int i = 0; i < 4; i++)
                acc[i] = fmaf(As[ty*4+i][kk], b, acc[i]);
        }
        __syncthreads();
    }
    #pragma unroll
    for (int i = 0; i < 4; i++)
        g_Gpre[(size_t)(row0 + ty*4 + i) * HD + tx] = acc[i];
#endif
}

// ---------------- gating mix + A (cooperative sigmoid) ---------------------
__global__ __launch_bounds__(256) void gate_kernel(const float* __restrict__ bG)
{
    __shared__ float sg[4][32];           // sigmoid gate values per token
    const int tid = threadIdx.x;
    const int nt0 = blockIdx.x * 4;

    if (tid < 128) {                      // one sigmoid per thread
        int tok = tid >> 5, j = tid & 31;
        float raw = g_Gpre[(size_t)(nt0 + tok) * HD + j] + bG[j];
        sg[tok][j] = 1.f / (1.f + __expf(-raw));
    }
    __syncthreads();

    if (tid < 16) {                       // A = 1 - sum_h g
        int tok = tid >> 2, e = tid & 3;
        float s = 0.f;
        #pragma unroll
        for (int h = 0; h < HH; h++) s += sg[tok][h*4 + e];
        int nt = nt0 + tok;
        int n = nt >> 11, t = nt & (TT - 1);
        g_A[(n*EE + e)*TT + t] = 1.f - s;
    }

    const int tok = tid >> 6;
    const int nt  = nt0 + tok;
    const int d   = tid & 63;
    const int n   = nt >> 11;
    const int t   = nt & (TT - 1);

    float sKv[4] = {0.f,0.f,0.f,0.f}, sVv[4] = {0.f,0.f,0.f,0.f};
    #pragma unroll
    for (int h = 0; h < HH; h++) {
        float kv = g_K[nt*HD + h*64 + d];
        float vv = g_V[nt*HD + h*64 + d];
        #pragma unroll
        for (int e = 0; e < EE; e++) {
            float g = sg[tok][h*4 + e];   // LDS broadcast within warp
            sKv[e] = fmaf(g, kv, sKv[e]);
            sVv[e] = fmaf(g, vv, sVv[e]);
        }
    }
    #pragma unroll
    for (int e = 0; e < EE; e++) {
        int o = ((n*EE + e)*TT + t) * DD + d;
        g_gK[o] = sKv[e];
        g_gV[o] = sVv[e];
    }
}

// ---------------- stride-32 recurrence (pipelined loads) -------------------
__global__ __launch_bounds__(256) void scan_kernel(
    const float* __restrict__ iK, const float* __restrict__ iV)
{
    const int idx = blockIdx.x * 256 + threadIdx.x;   // 32768 threads
    const int d = idx & 63;
    const int p = (idx >> 6) & 31;
    const int e = (idx >> 11) & 3;
    const int n = (idx >> 13) & 1;
    const int kv = idx >> 14;

    const float* init = kv ? iV : iK;
    const float* gsrc = kv ? g_gV : g_gK;
    __nv_bfloat16* dh = kv ? g_sVh : g_sKh;
    __nv_bfloat16* dl = kv ? g_sVl : g_sKl;

    float pk = init[(e*LL + p)*DD + d];
    const int rowbase = (n*EE + e) * TT;

    float aA[8], gA[8], aB[8], gB[8], aC[8], gC[8];
#define LOADG(av, gv, grp)                                          \
    _Pragma("unroll")                                               \
    for (int i = 0; i < 8; i++) {                                   \
        int t = ((grp)*8 + i)*LL + p;                               \
        av[i] = __ldg(&g_A[rowbase + t]);                           \
        gv[i] = __ldg(&gsrc[(rowbase + t)*DD + d]);                 \
    }
    LOADG(aA, gA, 0);
    LOADG(aB, gB, 1);
    #pragma unroll
    for (int m = 0; m < 8; m++) {        // 8 groups of 8 steps
        if (m + 2 < 8) { LOADG(aC, gC, m + 2); }
        #pragma unroll
        for (int i = 0; i < 8; i++) {
            pk = fmaf(aA[i], pk, gA[i]);
            __nv_bfloat16 h, l;
            split1(pk, h, l);
            int o = (rowbase + (m*8 + i)*LL + p)*DD + d;
            dh[o] = h; dl[o] = l;
        }
        #pragma unroll
        for (int i = 0; i < 8; i++) { aA[i] = aB[i]; gA[i] = gB[i];
                                      aB[i] = aC[i]; gB[i] = gC[i]; }
    }
#undef LOADG
}

// ---------------- launcher -------------------------------------------------
extern "C" void kernel_launch(void* const* d_in, const int* in_sizes, int n_in,
                              void* d_out, int out_size)
{
    const float* X  = (const float*)d_in[0];
    const float* wG = (const float*)d_in[1];
    const float* bG = (const float*)d_in[2];
    const float* wK = (const float*)d_in[3];
    const float* wV = (const float*)d_in[4];
    const float* wQ = (const float*)d_in[5];
    const float* wO = (const float*)d_in[6];
    const float* iK = (const float*)d_in[7];
    const float* iV = (const float*)d_in[8];
    float* out = (float*)d_out;
    (void)in_sizes; (void)n_in; (void)out_size;

    void *pXh, *pXl, *pWh, *pWl, *pWOh, *pWOl, *pYh, *pYl, *pK, *pV, *pQ, *pGp;
    cudaGetSymbolAddress(&pXh, g_Xh);   cudaGetSymbolAddress(&pXl, g_Xl);
    cudaGetSymbolAddress(&pWh, g_Wh);   cudaGetSymbolAddress(&pWl, g_Wl);
    cudaGetSymbolAddress(&pWOh, g_WOh); cudaGetSymbolAddress(&pWOl, g_WOl);
    cudaGetSymbolAddress(&pYh, g_Yh);   cudaGetSymbolAddress(&pYl, g_Yl);
    cudaGetSymbolAddress(&pK, g_K); cudaGetSymbolAddress(&pV, g_V);
    cudaGetSymbolAddress(&pQ, g_Q); cudaGetSymbolAddress(&pGp, g_Gpre);

    // On sm_10x the tcgen05 cubin is loaded; fallback launches are dead weight.
    int dev = 0, ccmaj = 0;
    cudaGetDevice(&dev);
    cudaDeviceGetAttribute(&ccmaj, cudaDevAttrComputeCapabilityMajor, dev);
    const bool tc = (ccmaj == 10);

    cudaFuncSetAttribute(attn_simt,
                         cudaFuncAttributeMaxDynamicSharedMemorySize, ATTN_SMEM);
    cudaFuncSetAttribute(attn_tc,
                         cudaFuncAttributeMaxDynamicSharedMemorySize, ATC_SMEM);
    cudaFuncSetAttribute(tc_gemm,
                         cudaFuncAttributeMaxDynamicSharedMemorySize, TC_SMEM);

    // split X + wK/wV/wQ + wG (+ zero pad) + wO transpose in ONE launch
    split_all<<<6272, 256>>>(X, wK, wV, wQ, wG, wO);

    // K/V/Q/G projections fused: 13 col tiles (12 proj + 1 G), occ-3, one wave
    tc_gemm<<<dim3(13, 32), 256, TC_SMEM>>>(
        (const __nv_bfloat16*)pXh, (const __nv_bfloat16*)pXl,
        (const __nv_bfloat16*)pWh, (const __nv_bfloat16*)pWl,
        DMD, (float*)pK, (float*)pV, (float*)pQ, (float*)pGp, HD);
    if (!tc) {
        sgemm128_tn<<<dim3(4, 32, 3), 256>>>(X, wK, wV, wQ);
        gproj_fb<<<128, 256>>>(X, wG);
    }

    gate_kernel<<<NT/4, 256>>>(bG);
    scan_kernel<<<128, 256>>>(iK, iV);

    attn_tc<<<dim3(TT/16, NB), 256, ATC_SMEM>>>(iK, iV);
    if (!tc)
        attn_simt<<<dim3(TT/TS, NB), 256, ATTN_SMEM>>>(iK, iV);

    // output projection out = Y @ wO (attn_tc wrote Yh/Yl directly)
    tc_gemm<<<dim3(8, 32), 256, TC_SMEM>>>(
        (const __nv_bfloat16*)pYh, (const __nv_bfloat16*)pYl,
        (const __nv_bfloat16*)pWOh, (const __nv_bfloat16*)pWOl,
        HD, out, out, out, out, DMD);
    if (!tc)
        sgemm128_nn<<<dim3(8, 32), 256>>>(wO, out);
}